// round 13
// baseline (speedup 1.0000x reference)
#include <cuda_runtime.h>
#include <cuda_bf16.h>
#include <math.h>
#include <stdint.h>

// ---------------------------------------------------------------------------
// TreeEncoder via mma.sync bf16 split-GEMM (hi/lo, 3 products, fp32 accum).
// Block tile 128x128, 256 threads, 8 warps as 4m x 2n of 32x64 warp tiles.
// Cuts ldsm/mma from 0.67 to 0.25 (L1 was 77.5% = binding pipe in R11).
// K-chunk 32, double-buffered cp.async staging, 80B-pitch smem, ldmatrix.
// ---------------------------------------------------------------------------

#define MAX_DEPTH 9
#define TOTAL 349525
#define OFF9  87381

__constant__ int c_off[11] = {0,1,5,21,85,341,1365,5461,21845,87381,349525};
// blocks per depth at 128 rows: 1,1,1,1,2,8,32,128,512,2048
__constant__ int c_embcum[11] = {0,1,2,3,4,6,14,46,174,686,2734};

static const int h_off[11]  = {0,1,5,21,85,341,1365,5461,21845,87381,349525};
static const int h_size[10] = {1,4,16,64,256,1024,4096,16384,65536,262144};

// ---------------- static scratch -------------------------------------------
__device__ float HBUF[TOTAL * 128];                       // in_proj fp32 (pool base)
__device__ __align__(16) __nv_bfloat16 HSH[TOTAL * 128];  // split of final h rows
__device__ __align__(16) __nv_bfloat16 HSL[TOTAL * 128];
__device__ __align__(16) __nv_bfloat16 HCH[OFF9 * 128];   // conv outputs split
__device__ __align__(16) __nv_bfloat16 HCL[OFF9 * 128];
__device__ __align__(16) __nv_bfloat16 XH[TOTAL * 64];    // posenc split (64-padded)
__device__ __align__(16) __nv_bfloat16 XL[TOTAL * 64];
// prepacked bf16 hi/lo weight chunk images: [tile][j=128][k=32]
__device__ __align__(16) __nv_bfloat16 WIH[2*4096],     WIL[2*4096];
__device__ __align__(16) __nv_bfloat16 WCH[10*36*4096], WCL[10*36*4096];
__device__ __align__(16) __nv_bfloat16 WEH[10*4*4096],  WEL[10*4*4096];

// ---------------- Morton helpers -------------------------------------------
__device__ __forceinline__ unsigned mi_interleave(unsigned x) {
    x &= 0xFFFFu;
    x = (x | (x << 8)) & 0x00FF00FFu;
    x = (x | (x << 4)) & 0x0F0F0F0Fu;
    x = (x | (x << 2)) & 0x33333333u;
    x = (x | (x << 1)) & 0x55555555u;
    return x;
}
__device__ __forceinline__ unsigned mi_deinterleave(unsigned x) {
    x &= 0x55555555u;
    x = (x | (x >> 1)) & 0x33333333u;
    x = (x | (x >> 2)) & 0x0F0F0F0Fu;
    x = (x | (x >> 4)) & 0x00FF00FFu;
    x = (x | (x >> 8)) & 0xFFFFu;
    return x;
}

// ---------------- PTX helpers ----------------------------------------------
__device__ __forceinline__ uint32_t smem_u32(const void* p) {
    uint32_t a;
    asm("{ .reg .u64 tmp; cvta.to.shared.u64 tmp, %1; cvt.u32.u64 %0, tmp; }"
        : "=r"(a) : "l"(p));
    return a;
}
__device__ __forceinline__ void ldsm4(uint32_t* r, uint32_t addr) {
    asm volatile("ldmatrix.sync.aligned.m8n8.x4.shared.b16 {%0,%1,%2,%3}, [%4];"
        : "=r"(r[0]), "=r"(r[1]), "=r"(r[2]), "=r"(r[3]) : "r"(addr));
}
__device__ __forceinline__ void mma_bf16(float* d, const uint32_t* a, const uint32_t* b) {
    asm volatile(
        "mma.sync.aligned.m16n8k16.row.col.f32.bf16.bf16.f32 "
        "{%0,%1,%2,%3}, {%4,%5,%6,%7}, {%8,%9}, {%0,%1,%2,%3};"
        : "+f"(d[0]), "+f"(d[1]), "+f"(d[2]), "+f"(d[3])
        : "r"(a[0]), "r"(a[1]), "r"(a[2]), "r"(a[3]), "r"(b[0]), "r"(b[1]));
}
__device__ __forceinline__ void cp16(uint32_t dst, const void* src, int srcsize) {
    asm volatile("cp.async.ca.shared.global [%0], [%1], 16, %2;"
                 :: "r"(dst), "l"(src), "r"(srcsize) : "memory");
}
#define CP_COMMIT() asm volatile("cp.async.commit_group;" ::: "memory")
#define CP_WAIT0()  asm volatile("cp.async.wait_group 0;" ::: "memory")

// ---------------- split helper ----------------------------------------------
__device__ __forceinline__ void split2(float a, float b, unsigned& hi, unsigned& lo) {
    __nv_bfloat162 h = __float22bfloat162_rn(make_float2(a, b));
    float2 f = __bfloat1622float2(h);
    __nv_bfloat162 l = __float22bfloat162_rn(make_float2(a - f.x, b - f.y));
    hi = *(unsigned*)&h;
    lo = *(unsigned*)&l;
}

// ---------------- smem buffer geometry --------------------------------------
// per-buffer: Ah[128*80] Al[128*80] Bh[128*80] Bl[128*80] = 40960 bytes, x2
#define BUFB 40960
#define DSM_BYTES (2 * BUFB)
#define AL_OFF 10240
#define BH_OFF 20480
#define BL_OFF 30720

// ---------------- shared compute: one 32-k chunk (warp tile 32m x 64n) ------
__device__ __forceinline__ void compute_chunk(uint32_t sb, int warp_m, int warp_n,
                                              int a_row, int a_byte,
                                              int b_row, int b_byte,
                                              float (*acc)[8][4]) {
    uint32_t Ah = sb, Al = sb + AL_OFF, Bh = sb + BH_OFF, Bl = sb + BL_OFF;
#pragma unroll
    for (int kt = 0; kt < 2; kt++) {
        uint32_t ah[2][4], al[2][4];
#pragma unroll
        for (int mt = 0; mt < 2; mt++) {
            uint32_t ao = (uint32_t)((warp_m * 32 + mt * 16 + a_row) * 80 + kt * 32 + a_byte);
            ldsm4(ah[mt], Ah + ao);
            ldsm4(al[mt], Al + ao);
        }
#pragma unroll
        for (int ng = 0; ng < 4; ng++) {
            uint32_t bo = (uint32_t)((warp_n * 64 + ng * 16 + b_row) * 80 + kt * 32 + b_byte);
            uint32_t bh[4], bl[4];
            ldsm4(bh, Bh + bo);
            ldsm4(bl, Bl + bo);
#pragma unroll
            for (int mt = 0; mt < 2; mt++) {
                mma_bf16(acc[mt][ng * 2 + 0], ah[mt], bh);
                mma_bf16(acc[mt][ng * 2 + 1], ah[mt], bh + 2);
            }
#pragma unroll
            for (int mt = 0; mt < 2; mt++) {
                mma_bf16(acc[mt][ng * 2 + 0], ah[mt], bl);
                mma_bf16(acc[mt][ng * 2 + 1], ah[mt], bl + 2);
            }
#pragma unroll
            for (int mt = 0; mt < 2; mt++) {
                mma_bf16(acc[mt][ng * 2 + 0], al[mt], bh);
                mma_bf16(acc[mt][ng * 2 + 1], al[mt], bh + 2);
            }
        }
    }
}

// ---------------- fused prep (weight split/pack) + posenc --------------------
#define NPI (128 * 64)
#define NPC (10 * 128 * 1152)
#define NPE (10 * 128 * 128)
#define PREP_TOTAL (NPI + NPC + NPE)
#define POSE_TOTAL (TOTAL * 64)
#define PP_TOTAL (PREP_TOTAL + POSE_TOTAL)

__global__ void prep_posenc_kernel(const float* __restrict__ in_proj_W,
                                   const float* __restrict__ conv_W,
                                   const float* __restrict__ emb_W,
                                   const float* __restrict__ feats) {
    int i0 = blockIdx.x * blockDim.x + threadIdx.x;
    if (i0 < PREP_TOTAL) {
        int i = i0;
        float val; int tile, j, kr;
        __nv_bfloat16 *WH, *WL;
        if (i < NPI) {
            j = i >> 6; int k = i & 63;
            tile = k >> 5; kr = k & 31;
            val = (k < 40) ? in_proj_W[j * 40 + k] : 0.f;
            WH = WIH; WL = WIL;
        } else if (i < NPI + NPC) {
            int r = i - NPI;
            int d = r / 147456;
            int rr = r % 147456;
            j = rr / 1152;
            int k = rr % 1152;
            tile = d * 36 + (k >> 5); kr = k & 31;
            val = conv_W[r];
            WH = WCH; WL = WCL;
        } else {
            int r = i - NPI - NPC;
            int d = r / 16384;
            int rr = r % 16384;
            j = rr >> 7;
            int k = rr & 127;
            tile = d * 4 + (k >> 5); kr = k & 31;
            val = emb_W[r];
            WH = WEH; WL = WEL;
        }
        __nv_bfloat16 hi = __float2bfloat16_rn(val);
        __nv_bfloat16 lo = __float2bfloat16_rn(val - __bfloat162float(hi));
        size_t idx = ((size_t)tile * 128 + j) * 32 + kr;
        WH[idx] = hi;
        WL[idx] = lo;
        return;
    }
    int i = i0 - PREP_TOTAL;
    if (i >= POSE_TOTAL) return;
    int node = i >> 6, c = i & 63;
    float v = 0.f;
    if (c < 40) {
        int d = 0;
        while (node >= c_off[d + 1]) d++;
        int local = node - c_off[d];
        if (c == 0) {
            v = feats[node];
        } else {
            unsigned ix = mi_deinterleave((unsigned)local);
            unsigned iy = mi_deinterleave((unsigned)local >> 1);
            float inv = 1.f / (float)(1 << d);
            float px = ((float)ix + 0.5f) * inv;
            float py = ((float)iy + 0.5f) * inv;
            float pd = (float)d * (1.f / 9.f);
            if (c == 1)      v = px;
            else if (c == 2) v = py;
            else if (c == 3) v = pd;
            else {
                int e = c - 4;
                int dim = e / 12, rem = e % 12;
                int f = rem % 6;
                float p = (dim == 0) ? px : (dim == 1) ? py : pd;
                float t = p * (float)(1 << f);
                float tr = t - rintf(t);
                v = (rem >= 6) ? cospif(2.f * tr) : sinpif(2.f * tr);
            }
        }
    }
    __nv_bfloat16 hi = __float2bfloat16_rn(v);
    __nv_bfloat16 lo = __float2bfloat16_rn(v - __bfloat162float(hi));
    XH[i] = hi;
    XL[i] = lo;
}

// ---------------- pooling d9 -> d8, writes HSH/HSL split --------------------
__global__ void pool9_kernel() {
    int u = blockIdx.x * blockDim.x + threadIdx.x;
    if (u >= 65536 * 32) return;
    int p = u >> 5, c4 = (u & 31) * 4;
    const float* s = HBUF + (size_t)(OFF9 + p * 4) * 128 + c4;
    float4 s0 = *(const float4*)(s);
    float4 s1 = *(const float4*)(s + 128);
    float4 s2 = *(const float4*)(s + 256);
    float4 s3 = *(const float4*)(s + 384);
    const float* bp = HBUF + (size_t)(21845 + p) * 128 + c4;
    float4 b = *(const float4*)bp;
    b.x += 0.25f * (s0.x + s1.x + s2.x + s3.x);
    b.y += 0.25f * (s0.y + s1.y + s2.y + s3.y);
    b.z += 0.25f * (s0.z + s1.z + s2.z + s3.z);
    b.w += 0.25f * (s0.w + s1.w + s2.w + s3.w);
    unsigned h0, l0, h1, l1;
    split2(b.x, b.y, h0, l0);
    split2(b.z, b.w, h1, l1);
    size_t o = (size_t)(21845 + p) * 128 + c4;
    *(uint2*)(HSH + o) = make_uint2(h0, h1);
    *(uint2*)(HSL + o) = make_uint2(l0, l1);
}

// ---------------- in_proj: X[N,64] @ W^T -> HBUF fp32 (+ split for d9) ------
__global__ __launch_bounds__(256, 2)
void inproj_mma(const float* __restrict__ bias) {
    extern __shared__ char dsm[];
    int t = threadIdx.x, lane = t & 31, wid = t >> 5;
    int warp_m = wid >> 1, warp_n = wid & 1;
    int base = blockIdx.x * 128;
    uint32_t sb0 = smem_u32(dsm);
    int a_row = (lane & 7) + ((lane >> 3) & 1) * 8, a_byte = (lane >> 4) * 16;
    int b_row = (lane & 7) + ((lane >> 4) & 1) * 8, b_byte = ((lane >> 3) & 1) * 16;
    int s_row = t >> 1, s_half = t & 1;

    float acc[2][8][4];
#pragma unroll
    for (int a = 0; a < 2; a++)
#pragma unroll
        for (int b = 0; b < 8; b++)
#pragma unroll
            for (int c = 0; c < 4; c++) acc[a][b][c] = 0.f;

    auto issue = [&](int chunk) {
        uint32_t bufu = sb0 + (chunk & 1) * BUFB;
        int node = base + s_row;
        int p = (node < TOTAL) ? 16 : 0;
        size_t ai = (size_t)(node < TOTAL ? node : 0) * 64 + chunk * 32 + s_half * 16;
        uint32_t ad = bufu + s_row * 80 + s_half * 32;
        cp16(ad, XH + ai, p);
        cp16(ad + 16, XH + ai + 8, p);
        cp16(ad + AL_OFF, XL + ai, p);
        cp16(ad + AL_OFF + 16, XL + ai + 8, p);
        size_t bi = ((size_t)chunk * 128 + s_row) * 32 + s_half * 16;
        uint32_t bd = bufu + BH_OFF + s_row * 80 + s_half * 32;
        cp16(bd, WIH + bi, 16);
        cp16(bd + 16, WIH + bi + 8, 16);
        cp16(bd + (BL_OFF - BH_OFF), WIL + bi, 16);
        cp16(bd + (BL_OFF - BH_OFF) + 16, WIL + bi + 8, 16);
    };

    const int KT = 2;
    issue(0); CP_COMMIT();
    for (int c = 0; c < KT; c++) {
        CP_WAIT0();
        __syncthreads();
        if (c + 1 < KT) { issue(c + 1); CP_COMMIT(); }
        compute_chunk(sb0 + (c & 1) * BUFB, warp_m, warp_n, a_row, a_byte, b_row, b_byte, acc);
    }

#pragma unroll
    for (int mt = 0; mt < 2; mt++)
#pragma unroll
        for (int nt = 0; nt < 8; nt++) {
            int col = warp_n * 64 + nt * 8 + (lane & 3) * 2;
            float b0v = bias[col], b1v = bias[col + 1];
            int r0 = base + warp_m * 32 + mt * 16 + (lane >> 2);
#pragma unroll
            for (int hrow = 0; hrow < 2; hrow++) {
                int node = r0 + hrow * 8;
                if (node < TOTAL) {
                    float v0 = acc[mt][nt][hrow * 2 + 0] + b0v;
                    float v1 = acc[mt][nt][hrow * 2 + 1] + b1v;
                    *(float2*)&HBUF[(size_t)node * 128 + col] = make_float2(v0, v1);
                    if (node >= OFF9) {
                        unsigned hh, ll;
                        split2(v0, v1, hh, ll);
                        *(unsigned*)&HSH[(size_t)node * 128 + col] = hh;
                        *(unsigned*)&HSL[(size_t)node * 128 + col] = ll;
                    }
                }
            }
        }
}

// ---------------- quadconv + fused pooling (parent split write) --------------
__global__ __launch_bounds__(256, 2)
void conv_mma(int depth, int off, int off_prev, int N, const float* __restrict__ conv_b) {
    extern __shared__ char dsm[];
    __shared__ int nbs[9 * 128];
    int t = threadIdx.x, lane = t & 31, wid = t >> 5;
    int warp_m = wid >> 1, warp_n = wid & 1;
    int base = blockIdx.x * 128;
    int res = 1 << depth;

    for (int e = t; e < 9 * 128; e += 256) {
        int m = e >> 7, r = e & 127;
        int node = base + r;
        int val = -1;
        if (node < N) {
            unsigned ix = mi_deinterleave((unsigned)node);
            unsigned iy = mi_deinterleave((unsigned)node >> 1);
            int dx = m % 3 - 1, dy = m / 3 - 1;
            int nx = (int)ix + dx, ny = (int)iy + dy;
            if (nx >= 0 && nx < res && ny >= 0 && ny < res)
                val = (int)(mi_interleave((unsigned)nx) | (mi_interleave((unsigned)ny) << 1));
        }
        nbs[m * 128 + r] = val;
    }
    __syncthreads();

    uint32_t sb0 = smem_u32(dsm);
    int a_row = (lane & 7) + ((lane >> 3) & 1) * 8, a_byte = (lane >> 4) * 16;
    int b_row = (lane & 7) + ((lane >> 4) & 1) * 8, b_byte = ((lane >> 3) & 1) * 16;
    int s_row = t >> 1, s_half = t & 1;
    int tbase = depth * 36;

    float acc[2][8][4];
#pragma unroll
    for (int a = 0; a < 2; a++)
#pragma unroll
        for (int b = 0; b < 8; b++)
#pragma unroll
            for (int c = 0; c < 4; c++) acc[a][b][c] = 0.f;

    auto issue = [&](int chunk) {
        uint32_t bufu = sb0 + (chunk & 1) * BUFB;
        int m = chunk >> 2, c0 = (chunk & 3) * 32;
        int nbi = nbs[m * 128 + s_row];
        int p = (nbi >= 0) ? 16 : 0;
        size_t ai = (size_t)(off + (nbi >= 0 ? nbi : 0)) * 128 + c0 + s_half * 16;
        uint32_t ad = bufu + s_row * 80 + s_half * 32;
        cp16(ad, HSH + ai, p);
        cp16(ad + 16, HSH + ai + 8, p);
        cp16(ad + AL_OFF, HSL + ai, p);
        cp16(ad + AL_OFF + 16, HSL + ai + 8, p);
        size_t bi = ((size_t)(tbase + chunk) * 128 + s_row) * 32 + s_half * 16;
        uint32_t bd = bufu + BH_OFF + s_row * 80 + s_half * 32;
        cp16(bd, WCH + bi, 16);
        cp16(bd + 16, WCH + bi + 8, 16);
        cp16(bd + (BL_OFF - BH_OFF), WCL + bi, 16);
        cp16(bd + (BL_OFF - BH_OFF) + 16, WCL + bi + 8, 16);
    };

    const int KT = 36;
    issue(0); CP_COMMIT();
    for (int c = 0; c < KT; c++) {
        CP_WAIT0();
        __syncthreads();
        if (c + 1 < KT) { issue(c + 1); CP_COMMIT(); }
        compute_chunk(sb0 + (c & 1) * BUFB, warp_m, warp_n, a_row, a_byte, b_row, b_byte, acc);
    }

    // epilogue: bias + relu -> HCH/HCL split; fused quad pooling -> HSH/HSL
#pragma unroll
    for (int mt = 0; mt < 2; mt++)
#pragma unroll
        for (int nt = 0; nt < 8; nt++) {
            int col = warp_n * 64 + nt * 8 + (lane & 3) * 2;
            float b0v = conv_b[depth * 128 + col], b1v = conv_b[depth * 128 + col + 1];
            int rl = warp_m * 32 + mt * 16 + (lane >> 2);
            float v00 = fmaxf(acc[mt][nt][0] + b0v, 0.f);
            float v01 = fmaxf(acc[mt][nt][1] + b1v, 0.f);
            float v10 = fmaxf(acc[mt][nt][2] + b0v, 0.f);
            float v11 = fmaxf(acc[mt][nt][3] + b1v, 0.f);
            if (base + rl < N) {
                unsigned hh, ll;
                split2(v00, v01, hh, ll);
                size_t o = (size_t)(off + base + rl) * 128 + col;
                *(unsigned*)&HCH[o] = hh;
                *(unsigned*)&HCL[o] = ll;
            }
            if (base + rl + 8 < N) {
                unsigned hh, ll;
                split2(v10, v11, hh, ll);
                size_t o = (size_t)(off + base + rl + 8) * 128 + col;
                *(unsigned*)&HCH[o] = hh;
                *(unsigned*)&HCL[o] = ll;
            }
            float s00 = v00; s00 += __shfl_xor_sync(~0u, s00, 4); s00 += __shfl_xor_sync(~0u, s00, 8);
            float s01 = v01; s01 += __shfl_xor_sync(~0u, s01, 4); s01 += __shfl_xor_sync(~0u, s01, 8);
            float s10 = v10; s10 += __shfl_xor_sync(~0u, s10, 4); s10 += __shfl_xor_sync(~0u, s10, 8);
            float s11 = v11; s11 += __shfl_xor_sync(~0u, s11, 4); s11 += __shfl_xor_sync(~0u, s11, 8);
            if ((lane & 12) == 0) {
#pragma unroll
                for (int g = 0; g < 2; g++) {
                    int q = base + rl + g * 8;
                    float sa = g ? s10 : s00, sb = g ? s11 : s01;
                    if (q + 3 < N) {
                        size_t o = (size_t)(off_prev + (q >> 2)) * 128 + col;
                        float pv0 = HBUF[o] + 0.25f * sa;
                        float pv1 = HBUF[o + 1] + 0.25f * sb;
                        unsigned hh, ll;
                        split2(pv0, pv1, hh, ll);
                        *(unsigned*)&HSH[o] = hh;
                        *(unsigned*)&HSL[o] = ll;
                    }
                }
            }
        }
}

// ---------------- emb GEMM + fused LayerNorm, all depths ---------------------
__global__ __launch_bounds__(256, 2)
void emb_mma(const float* __restrict__ emb_b,
             const float* __restrict__ ln_g,
             const float* __restrict__ ln_b,
             const float* __restrict__ gain_all,
             float* __restrict__ out) {
    extern __shared__ char dsm[];
    int t = threadIdx.x, lane = t & 31, wid = t >> 5;
    int warp_m = wid >> 1, warp_n = wid & 1;
    int b = blockIdx.x;
    int depth = 0;
    while (b >= c_embcum[depth + 1]) depth++;
    int base = (b - c_embcum[depth]) * 128;
    int off = c_off[depth];
    int N = c_off[depth + 1] - off;
    int useC = (depth >= 1 && depth <= 8);
    const __nv_bfloat16* SH = useC ? HCH : HSH;
    const __nv_bfloat16* SL = useC ? HCL : HSL;

    uint32_t sb0 = smem_u32(dsm);
    int a_row = (lane & 7) + ((lane >> 3) & 1) * 8, a_byte = (lane >> 4) * 16;
    int b_row = (lane & 7) + ((lane >> 4) & 1) * 8, b_byte = ((lane >> 3) & 1) * 16;
    int s_row = t >> 1, s_half = t & 1;
    int tbase = depth * 4;

    float acc[2][8][4];
#pragma unroll
    for (int a = 0; a < 2; a++)
#pragma unroll
        for (int bb = 0; bb < 8; bb++)
#pragma unroll
            for (int c = 0; c < 4; c++) acc[a][bb][c] = 0.f;

    auto issue = [&](int chunk) {
        uint32_t bufu = sb0 + (chunk & 1) * BUFB;
        int node = base + s_row;
        int p = (node < N) ? 16 : 0;
        size_t ai = (size_t)(off + (node < N ? node : 0)) * 128 + chunk * 32 + s_half * 16;
        uint32_t ad = bufu + s_row * 80 + s_half * 32;
        cp16(ad, SH + ai, p);
        cp16(ad + 16, SH + ai + 8, p);
        cp16(ad + AL_OFF, SL + ai, p);
        cp16(ad + AL_OFF + 16, SL + ai + 8, p);
        size_t bi = ((size_t)(tbase + chunk) * 128 + s_row) * 32 + s_half * 16;
        uint32_t bd = bufu + BH_OFF + s_row * 80 + s_half * 32;
        cp16(bd, WEH + bi, 16);
        cp16(bd + 16, WEH + bi + 8, 16);
        cp16(bd + (BL_OFF - BH_OFF), WEL + bi, 16);
        cp16(bd + (BL_OFF - BH_OFF) + 16, WEL + bi + 8, 16);
    };

    const int KT = 4;
    issue(0); CP_COMMIT();
    for (int c = 0; c < KT; c++) {
        CP_WAIT0();
        __syncthreads();
        if (c + 1 < KT) { issue(c + 1); CP_COMMIT(); }
        compute_chunk(sb0 + (c & 1) * BUFB, warp_m, warp_n, a_row, a_byte, b_row, b_byte, acc);
    }
    __syncthreads();

    // dump accumulators to smem [128][132]
    float* C = (float*)dsm;
#pragma unroll
    for (int mt = 0; mt < 2; mt++)
#pragma unroll
        for (int nt = 0; nt < 8; nt++) {
            int rl = warp_m * 32 + mt * 16 + (lane >> 2);
            int col = warp_n * 64 + nt * 8 + (lane & 3) * 2;
            C[rl * 132 + col] = acc[mt][nt][0];
            C[rl * 132 + col + 1] = acc[mt][nt][1];
            C[(rl + 8) * 132 + col] = acc[mt][nt][2];
            C[(rl + 8) * 132 + col + 1] = acc[mt][nt][3];
        }
    __syncthreads();

    // LayerNorm: two passes of 64 rows; thread owns (row, 32-col segment)
#pragma unroll
    for (int rh = 0; rh < 2; rh++) {
        int row = rh * 64 + (t >> 2), seg = t & 3;
        float z[32];
        const float* ebp = &emb_b[depth * 128 + seg * 32];
        float s = 0.f;
#pragma unroll
        for (int i = 0; i < 32; i++) {
            z[i] = C[row * 132 + seg * 32 + i] + ebp[i];
            s += z[i];
        }
        s += __shfl_xor_sync(~0u, s, 1);
        s += __shfl_xor_sync(~0u, s, 2);
        float mu = s * (1.f / 128.f);
        float q = 0.f;
#pragma unroll
        for (int i = 0; i < 32; i++) { z[i] -= mu; q += z[i] * z[i]; }
        q += __shfl_xor_sync(~0u, q, 1);
        q += __shfl_xor_sync(~0u, q, 2);
        float rs = rsqrtf(q * (1.f / 128.f) + 1e-5f);
        if (base + row < N) {
            const float* lgp = &ln_g[depth * 128 + seg * 32];
            const float* lbp = &ln_b[depth * 128 + seg * 32];
            float gain = gain_all[depth];
            float* dst = &out[(size_t)(off + base + row) * 128 + seg * 32];
#pragma unroll
            for (int i = 0; i < 32; i += 4) {
                float4 o;
                o.x = gain * (z[i] * rs * lgp[i] + lbp[i]);
                o.y = gain * (z[i + 1] * rs * lgp[i + 1] + lbp[i + 1]);
                o.z = gain * (z[i + 2] * rs * lgp[i + 2] + lbp[i + 2]);
                o.w = gain * (z[i + 3] * rs * lgp[i + 3] + lbp[i + 3]);
                *(float4*)(dst + i) = o;
            }
        }
    }
}

// ---------------------------------------------------------------------------
extern "C" void kernel_launch(void* const* d_in, const int* in_sizes, int n_in,
                              void* d_out, int out_size) {
    const float* feats     = (const float*)d_in[0];
    const float* in_proj_W = (const float*)d_in[1];
    const float* in_proj_b = (const float*)d_in[2];
    const float* conv_W    = (const float*)d_in[3];
    const float* conv_b    = (const float*)d_in[4];
    const float* emb_W     = (const float*)d_in[5];
    const float* emb_b     = (const float*)d_in[6];
    const float* ln_g      = (const float*)d_in[7];
    const float* ln_b      = (const float*)d_in[8];
    const float* gain      = (const float*)d_in[9];
    float* out = (float*)d_out;

    cudaFuncSetAttribute(inproj_mma, cudaFuncAttributeMaxDynamicSharedMemorySize, DSM_BYTES);
    cudaFuncSetAttribute(conv_mma, cudaFuncAttributeMaxDynamicSharedMemorySize, DSM_BYTES);
    cudaFuncSetAttribute(emb_mma, cudaFuncAttributeMaxDynamicSharedMemorySize, DSM_BYTES);

    prep_posenc_kernel<<<(PP_TOTAL + 255) / 256, 256>>>(in_proj_W, conv_W, emb_W, feats);
    inproj_mma<<<(TOTAL + 127) / 128, 256, DSM_BYTES>>>(in_proj_b);
    pool9_kernel<<<(65536 * 32 + 255) / 256, 256>>>();
    for (int dc = 8; dc >= 1; dc--)
        conv_mma<<<(h_size[dc] + 127) / 128, 256, DSM_BYTES>>>(dc, h_off[dc], h_off[dc - 1],
                                                               h_size[dc], conv_b);
    emb_mma<<<2734, 256, DSM_BYTES>>>(emb_b, ln_g, ln_b, gain, out);
}

// round 14
// speedup vs baseline: 1.2474x; 1.2474x over previous
#include <cuda_runtime.h>
#include <cuda_bf16.h>
#include <math.h>
#include <stdint.h>

// ---------------------------------------------------------------------------
// TreeEncoder via mma.sync bf16 split-GEMM (hi/lo, 3 products, fp32 accum).
// GEMM core = R11 winner: 64x128 block tile, 256 threads (8 warps, 32x32 warp
// tiles), K-chunk 32, NBUF=2 cp.async double buffer, launch_bounds(256,3).
// R14 change: posenc rewritten one-thread-per-node with sin/cos angle-doubling
// (6 MUFU/node instead of 36; no per-element depth search / deinterleave).
// ---------------------------------------------------------------------------

#define MAX_DEPTH 9
#define TOTAL 349525
#define OFF9  87381

__constant__ int c_off[11] = {0,1,5,21,85,341,1365,5461,21845,87381,349525};
// blocks per depth at 64 rows: 1,1,1,1,4,16,64,256,1024,4096
__constant__ int c_embcum[11] = {0,1,2,3,4,8,24,88,344,1368,5464};

static const int h_off[11]  = {0,1,5,21,85,341,1365,5461,21845,87381,349525};
static const int h_size[10] = {1,4,16,64,256,1024,4096,16384,65536,262144};

// ---------------- static scratch -------------------------------------------
__device__ float HBUF[TOTAL * 128];                       // in_proj fp32 (pool base)
__device__ __align__(16) __nv_bfloat16 HSH[TOTAL * 128];  // split of final h rows
__device__ __align__(16) __nv_bfloat16 HSL[TOTAL * 128];
__device__ __align__(16) __nv_bfloat16 HCH[OFF9 * 128];   // conv outputs split
__device__ __align__(16) __nv_bfloat16 HCL[OFF9 * 128];
__device__ __align__(16) __nv_bfloat16 XH[TOTAL * 64];    // posenc split (64-padded)
__device__ __align__(16) __nv_bfloat16 XL[TOTAL * 64];
// prepacked bf16 hi/lo weight chunk images: [tile][j=128][k=32]
__device__ __align__(16) __nv_bfloat16 WIH[2*4096],     WIL[2*4096];
__device__ __align__(16) __nv_bfloat16 WCH[10*36*4096], WCL[10*36*4096];
__device__ __align__(16) __nv_bfloat16 WEH[10*4*4096],  WEL[10*4*4096];

// ---------------- Morton helpers -------------------------------------------
__device__ __forceinline__ unsigned mi_interleave(unsigned x) {
    x &= 0xFFFFu;
    x = (x | (x << 8)) & 0x00FF00FFu;
    x = (x | (x << 4)) & 0x0F0F0F0Fu;
    x = (x | (x << 2)) & 0x33333333u;
    x = (x | (x << 1)) & 0x55555555u;
    return x;
}
__device__ __forceinline__ unsigned mi_deinterleave(unsigned x) {
    x &= 0x55555555u;
    x = (x | (x >> 1)) & 0x33333333u;
    x = (x | (x >> 2)) & 0x0F0F0F0Fu;
    x = (x | (x >> 4)) & 0x00FF00FFu;
    x = (x | (x >> 8)) & 0xFFFFu;
    return x;
}

// ---------------- PTX helpers ----------------------------------------------
__device__ __forceinline__ uint32_t smem_u32(const void* p) {
    uint32_t a;
    asm("{ .reg .u64 tmp; cvta.to.shared.u64 tmp, %1; cvt.u32.u64 %0, tmp; }"
        : "=r"(a) : "l"(p));
    return a;
}
__device__ __forceinline__ void ldsm4(uint32_t* r, uint32_t addr) {
    asm volatile("ldmatrix.sync.aligned.m8n8.x4.shared.b16 {%0,%1,%2,%3}, [%4];"
        : "=r"(r[0]), "=r"(r[1]), "=r"(r[2]), "=r"(r[3]) : "r"(addr));
}
__device__ __forceinline__ void mma_bf16(float* d, const uint32_t* a, const uint32_t* b) {
    asm volatile(
        "mma.sync.aligned.m16n8k16.row.col.f32.bf16.bf16.f32 "
        "{%0,%1,%2,%3}, {%4,%5,%6,%7}, {%8,%9}, {%0,%1,%2,%3};"
        : "+f"(d[0]), "+f"(d[1]), "+f"(d[2]), "+f"(d[3])
        : "r"(a[0]), "r"(a[1]), "r"(a[2]), "r"(a[3]), "r"(b[0]), "r"(b[1]));
}
__device__ __forceinline__ void cp16(uint32_t dst, const void* src, int srcsize) {
    asm volatile("cp.async.ca.shared.global [%0], [%1], 16, %2;"
                 :: "r"(dst), "l"(src), "r"(srcsize) : "memory");
}
#define CP_COMMIT() asm volatile("cp.async.commit_group;" ::: "memory")
#define CP_WAIT0()  asm volatile("cp.async.wait_group 0;" ::: "memory")

// ---------------- split helper ----------------------------------------------
__device__ __forceinline__ void split2(float a, float b, unsigned& hi, unsigned& lo) {
    __nv_bfloat162 h = __float22bfloat162_rn(make_float2(a, b));
    float2 f = __bfloat1622float2(h);
    __nv_bfloat162 l = __float22bfloat162_rn(make_float2(a - f.x, b - f.y));
    hi = *(unsigned*)&h;
    lo = *(unsigned*)&l;
}

// ---------------- smem buffer geometry --------------------------------------
// per-buffer: Ah[64*80] Al[64*80] Bh[128*80] Bl[128*80] = 30720 bytes, x2 bufs
#define BUFB 30720
#define NBUF 2
#define DSM_BYTES (NBUF * BUFB)
#define AL_OFF 5120
#define BH_OFF 10240
#define BL_OFF 20480

// ---------------- shared compute: one 32-k chunk (per warp 32x32 tile) ------
__device__ __forceinline__ void compute_chunk(uint32_t sb, int warp_m, int warp_n,
                                              int a_row, int a_byte,
                                              int b_row, int b_byte,
                                              float (*acc)[4][4]) {
    uint32_t Ah = sb, Al = sb + AL_OFF, Bh = sb + BH_OFF, Bl = sb + BL_OFF;
#pragma unroll
    for (int kt = 0; kt < 2; kt++) {
        uint32_t ah[2][4], al[2][4];
#pragma unroll
        for (int mt = 0; mt < 2; mt++) {
            uint32_t ao = (uint32_t)((warp_m * 32 + mt * 16 + a_row) * 80 + kt * 32 + a_byte);
            ldsm4(ah[mt], Ah + ao);
            ldsm4(al[mt], Al + ao);
        }
#pragma unroll
        for (int ng = 0; ng < 2; ng++) {
            uint32_t bo = (uint32_t)((warp_n * 32 + ng * 16 + b_row) * 80 + kt * 32 + b_byte);
            uint32_t bh[4], bl[4];
            ldsm4(bh, Bh + bo);
            ldsm4(bl, Bl + bo);
#pragma unroll
            for (int mt = 0; mt < 2; mt++) {
                mma_bf16(acc[mt][ng * 2 + 0], ah[mt], bh);
                mma_bf16(acc[mt][ng * 2 + 1], ah[mt], bh + 2);
            }
#pragma unroll
            for (int mt = 0; mt < 2; mt++) {
                mma_bf16(acc[mt][ng * 2 + 0], ah[mt], bl);
                mma_bf16(acc[mt][ng * 2 + 1], ah[mt], bl + 2);
            }
#pragma unroll
            for (int mt = 0; mt < 2; mt++) {
                mma_bf16(acc[mt][ng * 2 + 0], al[mt], bh);
                mma_bf16(acc[mt][ng * 2 + 1], al[mt], bh + 2);
            }
        }
    }
}

// ---------------- fused prep (weight split/pack) + per-node posenc -----------
#define NPI (128 * 64)
#define NPC (10 * 128 * 1152)
#define NPE (10 * 128 * 128)
#define PREP_TOTAL (NPI + NPC + NPE)
#define PP_TOTAL (PREP_TOTAL + TOTAL)

__global__ void prep_posenc_kernel(const float* __restrict__ in_proj_W,
                                   const float* __restrict__ conv_W,
                                   const float* __restrict__ emb_W,
                                   const float* __restrict__ feats) {
    int i0 = blockIdx.x * blockDim.x + threadIdx.x;
    if (i0 < PREP_TOTAL) {
        int i = i0;
        float val; int tile, j, kr;
        __nv_bfloat16 *WH, *WL;
        if (i < NPI) {
            j = i >> 6; int k = i & 63;
            tile = k >> 5; kr = k & 31;
            val = (k < 40) ? in_proj_W[j * 40 + k] : 0.f;
            WH = WIH; WL = WIL;
        } else if (i < NPI + NPC) {
            int r = i - NPI;
            int d = r / 147456;
            int rr = r % 147456;
            j = rr / 1152;
            int k = rr % 1152;
            tile = d * 36 + (k >> 5); kr = k & 31;
            val = conv_W[r];
            WH = WCH; WL = WCL;
        } else {
            int r = i - NPI - NPC;
            int d = r / 16384;
            int rr = r % 16384;
            j = rr >> 7;
            int k = rr & 127;
            tile = d * 4 + (k >> 5); kr = k & 31;
            val = emb_W[r];
            WH = WEH; WL = WEL;
        }
        __nv_bfloat16 hi = __float2bfloat16_rn(val);
        __nv_bfloat16 lo = __float2bfloat16_rn(val - __bfloat162float(hi));
        size_t idx = ((size_t)tile * 128 + j) * 32 + kr;
        WH[idx] = hi;
        WL[idx] = lo;
        return;
    }
    int node = i0 - PREP_TOTAL;
    if (node >= TOTAL) return;

    // one thread per node: all 40 real columns + 24 zero pad
    int d = 0;
    while (node >= c_off[d + 1]) d++;
    int local = node - c_off[d];
    unsigned ix = mi_deinterleave((unsigned)local);
    unsigned iy = mi_deinterleave((unsigned)local >> 1);
    float inv = 1.f / (float)(1 << d);

    float vals[64];
#pragma unroll
    for (int c = 40; c < 64; c++) vals[c] = 0.f;
    vals[0] = feats[node];
    vals[1] = ((float)ix + 0.5f) * inv;
    vals[2] = ((float)iy + 0.5f) * inv;
    vals[3] = (float)d * (1.f / 9.f);

#pragma unroll
    for (int dim = 0; dim < 3; dim++) {
        float p = vals[1 + dim];
        // s = sin(2*pi*p*2^f), c = cos(...) by angle doubling from f=0
        float s = sinpif(2.f * p);
        float cc = cospif(2.f * p);
#pragma unroll
        for (int f = 0; f < 6; f++) {
            vals[4 + dim * 12 + f] = s;
            vals[4 + dim * 12 + 6 + f] = cc;
            float s2 = 2.f * s * cc;
            float c2 = fmaf(2.f * cc, cc, -1.f);
            s = s2;
            cc = c2;
        }
    }

    // split to bf16 hi/lo, vectorized stores (8 values -> one uint4 per buffer)
#pragma unroll
    for (int g = 0; g < 8; g++) {
        unsigned h[4], l[4];
#pragma unroll
        for (int q = 0; q < 4; q++)
            split2(vals[g * 8 + 2 * q], vals[g * 8 + 2 * q + 1], h[q], l[q]);
        *(uint4*)(XH + (size_t)node * 64 + g * 8) = make_uint4(h[0], h[1], h[2], h[3]);
        *(uint4*)(XL + (size_t)node * 64 + g * 8) = make_uint4(l[0], l[1], l[2], l[3]);
    }
}

// ---------------- pooling d9 -> d8, writes HSH/HSL split --------------------
__global__ void pool9_kernel() {
    int u = blockIdx.x * blockDim.x + threadIdx.x;
    if (u >= 65536 * 32) return;
    int p = u >> 5, c4 = (u & 31) * 4;
    const float* s = HBUF + (size_t)(OFF9 + p * 4) * 128 + c4;
    float4 s0 = *(const float4*)(s);
    float4 s1 = *(const float4*)(s + 128);
    float4 s2 = *(const float4*)(s + 256);
    float4 s3 = *(const float4*)(s + 384);
    const float* bp = HBUF + (size_t)(21845 + p) * 128 + c4;
    float4 b = *(const float4*)bp;
    b.x += 0.25f * (s0.x + s1.x + s2.x + s3.x);
    b.y += 0.25f * (s0.y + s1.y + s2.y + s3.y);
    b.z += 0.25f * (s0.z + s1.z + s2.z + s3.z);
    b.w += 0.25f * (s0.w + s1.w + s2.w + s3.w);
    unsigned h0, l0, h1, l1;
    split2(b.x, b.y, h0, l0);
    split2(b.z, b.w, h1, l1);
    size_t o = (size_t)(21845 + p) * 128 + c4;
    *(uint2*)(HSH + o) = make_uint2(h0, h1);
    *(uint2*)(HSL + o) = make_uint2(l0, l1);
}

// ---------------- in_proj: X[N,64] @ W^T -> HBUF fp32 (+ split for d9) ------
__global__ __launch_bounds__(256, 3)
void inproj_mma(const float* __restrict__ bias) {
    extern __shared__ char dsm[];
    int t = threadIdx.x, lane = t & 31, wid = t >> 5;
    int warp_m = wid >> 2, warp_n = wid & 3;
    int base = blockIdx.x * 64;
    uint32_t sb0 = smem_u32(dsm);
    int a_row = (lane & 7) + ((lane >> 3) & 1) * 8, a_byte = (lane >> 4) * 16;
    int b_row = (lane & 7) + ((lane >> 4) & 1) * 8, b_byte = ((lane >> 3) & 1) * 16;
    int s_row = t >> 2, s_seg = t & 3;

    float acc[2][4][4];
#pragma unroll
    for (int a = 0; a < 2; a++)
#pragma unroll
        for (int b = 0; b < 4; b++)
#pragma unroll
            for (int c = 0; c < 4; c++) acc[a][b][c] = 0.f;

    auto issue = [&](int chunk) {
        uint32_t bufu = sb0 + (chunk & 1) * BUFB;
        int node = base + s_row;
        int p = (node < TOTAL) ? 16 : 0;
        size_t ai = (size_t)(node < TOTAL ? node : 0) * 64 + chunk * 32 + s_seg * 8;
        uint32_t ad = bufu + s_row * 80 + s_seg * 16;
        cp16(ad, XH + ai, p);
        cp16(ad + AL_OFF, XL + ai, p);
#pragma unroll
        for (int h = 0; h < 2; h++) {
            int j = s_row + h * 64;
            size_t bi = ((size_t)chunk * 128 + j) * 32 + s_seg * 8;
            uint32_t bd = bufu + BH_OFF + j * 80 + s_seg * 16;
            cp16(bd, WIH + bi, 16);
            cp16(bd + (BL_OFF - BH_OFF), WIL + bi, 16);
        }
    };

    const int KT = 2;
    issue(0); CP_COMMIT();
    for (int c = 0; c < KT; c++) {
        CP_WAIT0();
        __syncthreads();
        if (c + 1 < KT) { issue(c + 1); CP_COMMIT(); }
        compute_chunk(sb0 + (c & 1) * BUFB, warp_m, warp_n, a_row, a_byte, b_row, b_byte, acc);
    }

#pragma unroll
    for (int mt = 0; mt < 2; mt++)
#pragma unroll
        for (int nt = 0; nt < 4; nt++) {
            int col = warp_n * 32 + nt * 8 + (lane & 3) * 2;
            float b0v = bias[col], b1v = bias[col + 1];
            int r0 = base + warp_m * 32 + mt * 16 + (lane >> 2);
#pragma unroll
            for (int hrow = 0; hrow < 2; hrow++) {
                int node = r0 + hrow * 8;
                if (node < TOTAL) {
                    float v0 = acc[mt][nt][hrow * 2 + 0] + b0v;
                    float v1 = acc[mt][nt][hrow * 2 + 1] + b1v;
                    *(float2*)&HBUF[(size_t)node * 128 + col] = make_float2(v0, v1);
                    if (node >= OFF9) {
                        unsigned hh, ll;
                        split2(v0, v1, hh, ll);
                        *(unsigned*)&HSH[(size_t)node * 128 + col] = hh;
                        *(unsigned*)&HSL[(size_t)node * 128 + col] = ll;
                    }
                }
            }
        }
}

// ---------------- quadconv + fused pooling (parent split write) --------------
__global__ __launch_bounds__(256, 3)
void conv_mma(int depth, int off, int off_prev, int N, const float* __restrict__ conv_b) {
    extern __shared__ char dsm[];
    __shared__ int nbs[9 * 64];
    int t = threadIdx.x, lane = t & 31, wid = t >> 5;
    int warp_m = wid >> 2, warp_n = wid & 3;
    int base = blockIdx.x * 64;
    int res = 1 << depth;

    for (int e = t; e < 9 * 64; e += 256) {
        int m = e >> 6, r = e & 63;
        int node = base + r;
        int val = -1;
        if (node < N) {
            unsigned ix = mi_deinterleave((unsigned)node);
            unsigned iy = mi_deinterleave((unsigned)node >> 1);
            int dx = m % 3 - 1, dy = m / 3 - 1;
            int nx = (int)ix + dx, ny = (int)iy + dy;
            if (nx >= 0 && nx < res && ny >= 0 && ny < res)
                val = (int)(mi_interleave((unsigned)nx) | (mi_interleave((unsigned)ny) << 1));
        }
        nbs[m * 64 + r] = val;
    }
    __syncthreads();

    uint32_t sb0 = smem_u32(dsm);
    int a_row = (lane & 7) + ((lane >> 3) & 1) * 8, a_byte = (lane >> 4) * 16;
    int b_row = (lane & 7) + ((lane >> 4) & 1) * 8, b_byte = ((lane >> 3) & 1) * 16;
    int s_row = t >> 2, s_seg = t & 3;
    int tbase = depth * 36;

    float acc[2][4][4];
#pragma unroll
    for (int a = 0; a < 2; a++)
#pragma unroll
        for (int b = 0; b < 4; b++)
#pragma unroll
            for (int c = 0; c < 4; c++) acc[a][b][c] = 0.f;

    auto issue = [&](int chunk) {
        uint32_t bufu = sb0 + (chunk & 1) * BUFB;
        int m = chunk >> 2, c0 = (chunk & 3) * 32;
        int nbi = nbs[m * 64 + s_row];
        int p = (nbi >= 0) ? 16 : 0;
        size_t ai = (size_t)(off + (nbi >= 0 ? nbi : 0)) * 128 + c0 + s_seg * 8;
        uint32_t ad = bufu + s_row * 80 + s_seg * 16;
        cp16(ad, HSH + ai, p);
        cp16(ad + AL_OFF, HSL + ai, p);
#pragma unroll
        for (int h = 0; h < 2; h++) {
            int j = s_row + h * 64;
            size_t bi = ((size_t)(tbase + chunk) * 128 + j) * 32 + s_seg * 8;
            uint32_t bd = bufu + BH_OFF + j * 80 + s_seg * 16;
            cp16(bd, WCH + bi, 16);
            cp16(bd + (BL_OFF - BH_OFF), WCL + bi, 16);
        }
    };

    const int KT = 36;
    issue(0); CP_COMMIT();
    for (int c = 0; c < KT; c++) {
        CP_WAIT0();
        __syncthreads();
        if (c + 1 < KT) { issue(c + 1); CP_COMMIT(); }
        compute_chunk(sb0 + (c & 1) * BUFB, warp_m, warp_n, a_row, a_byte, b_row, b_byte, acc);
    }

    // epilogue: bias + relu -> HCH/HCL split; fused quad pooling -> HSH/HSL
#pragma unroll
    for (int mt = 0; mt < 2; mt++)
#pragma unroll
        for (int nt = 0; nt < 4; nt++) {
            int col = warp_n * 32 + nt * 8 + (lane & 3) * 2;
            float b0v = conv_b[depth * 128 + col], b1v = conv_b[depth * 128 + col + 1];
            int rl = warp_m * 32 + mt * 16 + (lane >> 2);
            float v00 = fmaxf(acc[mt][nt][0] + b0v, 0.f);
            float v01 = fmaxf(acc[mt][nt][1] + b1v, 0.f);
            float v10 = fmaxf(acc[mt][nt][2] + b0v, 0.f);
            float v11 = fmaxf(acc[mt][nt][3] + b1v, 0.f);
            if (base + rl < N) {
                unsigned hh, ll;
                split2(v00, v01, hh, ll);
                size_t o = (size_t)(off + base + rl) * 128 + col;
                *(unsigned*)&HCH[o] = hh;
                *(unsigned*)&HCL[o] = ll;
            }
            if (base + rl + 8 < N) {
                unsigned hh, ll;
                split2(v10, v11, hh, ll);
                size_t o = (size_t)(off + base + rl + 8) * 128 + col;
                *(unsigned*)&HCH[o] = hh;
                *(unsigned*)&HCL[o] = ll;
            }
            float s00 = v00; s00 += __shfl_xor_sync(~0u, s00, 4); s00 += __shfl_xor_sync(~0u, s00, 8);
            float s01 = v01; s01 += __shfl_xor_sync(~0u, s01, 4); s01 += __shfl_xor_sync(~0u, s01, 8);
            float s10 = v10; s10 += __shfl_xor_sync(~0u, s10, 4); s10 += __shfl_xor_sync(~0u, s10, 8);
            float s11 = v11; s11 += __shfl_xor_sync(~0u, s11, 4); s11 += __shfl_xor_sync(~0u, s11, 8);
            if ((lane & 12) == 0) {
#pragma unroll
                for (int g = 0; g < 2; g++) {
                    int q = base + rl + g * 8;
                    float sa = g ? s10 : s00, sb = g ? s11 : s01;
                    if (q + 3 < N) {
                        size_t o = (size_t)(off_prev + (q >> 2)) * 128 + col;
                        float pv0 = HBUF[o] + 0.25f * sa;
                        float pv1 = HBUF[o + 1] + 0.25f * sb;
                        unsigned hh, ll;
                        split2(pv0, pv1, hh, ll);
                        *(unsigned*)&HSH[o] = hh;
                        *(unsigned*)&HSL[o] = ll;
                    }
                }
            }
        }
}

// ---------------- emb GEMM + fused LayerNorm, all depths ---------------------
__global__ __launch_bounds__(256, 3)
void emb_mma(const float* __restrict__ emb_b,
             const float* __restrict__ ln_g,
             const float* __restrict__ ln_b,
             const float* __restrict__ gain_all,
             float* __restrict__ out) {
    extern __shared__ char dsm[];
    int t = threadIdx.x, lane = t & 31, wid = t >> 5;
    int warp_m = wid >> 2, warp_n = wid & 3;
    int b = blockIdx.x;
    int depth = 0;
    while (b >= c_embcum[depth + 1]) depth++;
    int base = (b - c_embcum[depth]) * 64;
    int off = c_off[depth];
    int N = c_off[depth + 1] - off;
    int useC = (depth >= 1 && depth <= 8);
    const __nv_bfloat16* SH = useC ? HCH : HSH;
    const __nv_bfloat16* SL = useC ? HCL : HSL;

    uint32_t sb0 = smem_u32(dsm);
    int a_row = (lane & 7) + ((lane >> 3) & 1) * 8, a_byte = (lane >> 4) * 16;
    int b_row = (lane & 7) + ((lane >> 4) & 1) * 8, b_byte = ((lane >> 3) & 1) * 16;
    int s_row = t >> 2, s_seg = t & 3;
    int tbase = depth * 4;

    float acc[2][4][4];
#pragma unroll
    for (int a = 0; a < 2; a++)
#pragma unroll
        for (int bb = 0; bb < 4; bb++)
#pragma unroll
            for (int c = 0; c < 4; c++) acc[a][bb][c] = 0.f;

    auto issue = [&](int chunk) {
        uint32_t bufu = sb0 + (chunk & 1) * BUFB;
        int node = base + s_row;
        int p = (node < N) ? 16 : 0;
        size_t ai = (size_t)(off + (node < N ? node : 0)) * 128 + chunk * 32 + s_seg * 8;
        uint32_t ad = bufu + s_row * 80 + s_seg * 16;
        cp16(ad, SH + ai, p);
        cp16(ad + AL_OFF, SL + ai, p);
#pragma unroll
        for (int h = 0; h < 2; h++) {
            int j = s_row + h * 64;
            size_t bi = ((size_t)(tbase + chunk) * 128 + j) * 32 + s_seg * 8;
            uint32_t bd = bufu + BH_OFF + j * 80 + s_seg * 16;
            cp16(bd, WEH + bi, 16);
            cp16(bd + (BL_OFF - BH_OFF), WEL + bi, 16);
        }
    };

    const int KT = 4;
    issue(0); CP_COMMIT();
    for (int c = 0; c < KT; c++) {
        CP_WAIT0();
        __syncthreads();
        if (c + 1 < KT) { issue(c + 1); CP_COMMIT(); }
        compute_chunk(sb0 + (c & 1) * BUFB, warp_m, warp_n, a_row, a_byte, b_row, b_byte, acc);
    }
    __syncthreads();

    // dump accumulators to smem [64][132]
    float* C = (float*)dsm;
#pragma unroll
    for (int mt = 0; mt < 2; mt++)
#pragma unroll
        for (int nt = 0; nt < 4; nt++) {
            int rl = warp_m * 32 + mt * 16 + (lane >> 2);
            int col = warp_n * 32 + nt * 8 + (lane & 3) * 2;
            C[rl * 132 + col] = acc[mt][nt][0];
            C[rl * 132 + col + 1] = acc[mt][nt][1];
            C[(rl + 8) * 132 + col] = acc[mt][nt][2];
            C[(rl + 8) * 132 + col + 1] = acc[mt][nt][3];
        }
    __syncthreads();

    // LayerNorm: thread owns (row = t>>2, 32-col segment = t&3)
    int row = t >> 2, seg = t & 3;
    float z[32];
    const float* ebp = &emb_b[depth * 128 + seg * 32];
    float s = 0.f;
#pragma unroll
    for (int i = 0; i < 32; i++) {
        z[i] = C[row * 132 + seg * 32 + i] + ebp[i];
        s += z[i];
    }
    s += __shfl_xor_sync(~0u, s, 1);
    s += __shfl_xor_sync(~0u, s, 2);
    float mu = s * (1.f / 128.f);
    float q = 0.f;
#pragma unroll
    for (int i = 0; i < 32; i++) { z[i] -= mu; q += z[i] * z[i]; }
    q += __shfl_xor_sync(~0u, q, 1);
    q += __shfl_xor_sync(~0u, q, 2);
    float rs = rsqrtf(q * (1.f / 128.f) + 1e-5f);
    if (base + row < N) {
        const float* lgp = &ln_g[depth * 128 + seg * 32];
        const float* lbp = &ln_b[depth * 128 + seg * 32];
        float gain = gain_all[depth];
        float* dst = &out[(size_t)(off + base + row) * 128 + seg * 32];
#pragma unroll
        for (int i = 0; i < 32; i += 4) {
            float4 o;
            o.x = gain * (z[i] * rs * lgp[i] + lbp[i]);
            o.y = gain * (z[i + 1] * rs * lgp[i + 1] + lbp[i + 1]);
            o.z = gain * (z[i + 2] * rs * lgp[i + 2] + lbp[i + 2]);
            o.w = gain * (z[i + 3] * rs * lgp[i + 3] + lbp[i + 3]);
            *(float4*)(dst + i) = o;
        }
    }
}

// ---------------------------------------------------------------------------
extern "C" void kernel_launch(void* const* d_in, const int* in_sizes, int n_in,
                              void* d_out, int out_size) {
    const float* feats     = (const float*)d_in[0];
    const float* in_proj_W = (const float*)d_in[1];
    const float* in_proj_b = (const float*)d_in[2];
    const float* conv_W    = (const float*)d_in[3];
    const float* conv_b    = (const float*)d_in[4];
    const float* emb_W     = (const float*)d_in[5];
    const float* emb_b     = (const float*)d_in[6];
    const float* ln_g      = (const float*)d_in[7];
    const float* ln_b      = (const float*)d_in[8];
    const float* gain      = (const float*)d_in[9];
    float* out = (float*)d_out;

    cudaFuncSetAttribute(inproj_mma, cudaFuncAttributeMaxDynamicSharedMemorySize, DSM_BYTES);
    cudaFuncSetAttribute(conv_mma, cudaFuncAttributeMaxDynamicSharedMemorySize, DSM_BYTES);
    cudaFuncSetAttribute(emb_mma, cudaFuncAttributeMaxDynamicSharedMemorySize, DSM_BYTES);

    prep_posenc_kernel<<<(PP_TOTAL + 255) / 256, 256>>>(in_proj_W, conv_W, emb_W, feats);
    inproj_mma<<<(TOTAL + 63) / 64, 256, DSM_BYTES>>>(in_proj_b);
    pool9_kernel<<<(65536 * 32 + 255) / 256, 256>>>();
    for (int dc = 8; dc >= 1; dc--)
        conv_mma<<<(h_size[dc] + 63) / 64, 256, DSM_BYTES>>>(dc, h_off[dc], h_off[dc - 1],
                                                             h_size[dc], conv_b);
    emb_mma<<<5464, 256, DSM_BYTES>>>(emb_b, ln_g, ln_b, gain, out);
}

// round 15
// speedup vs baseline: 1.4761x; 1.1833x over previous
#include <cuda_runtime.h>
#include <cuda_bf16.h>
#include <math.h>
#include <stdint.h>

// ---------------------------------------------------------------------------
// TreeEncoder via mma.sync bf16 split-GEMM (hi/lo, 3 products, fp32 accum).
// GEMM core = R11/R14 winner: 64x128 block tile, 256 threads, K-chunk 32,
// NBUF=2 cp.async double buffer, launch_bounds(256,3).
// R15: depths 1..6 use split-K (KS=6) conv into fp32 partial slices + a tiny
// reduce/pool epilogue -- removes the 36-chunk serial K-loop on tiny grids.
// ---------------------------------------------------------------------------

#define MAX_DEPTH 9
#define TOTAL 349525
#define OFF9  87381
#define KS 6
#define SLICE (5461 * 128)   // covers nodes of depths 0..6 (off+N <= 5461)

__constant__ int c_off[11] = {0,1,5,21,85,341,1365,5461,21845,87381,349525};
// blocks per depth at 64 rows: 1,1,1,1,4,16,64,256,1024,4096
__constant__ int c_embcum[11] = {0,1,2,3,4,8,24,88,344,1368,5464};

static const int h_off[11]  = {0,1,5,21,85,341,1365,5461,21845,87381,349525};
static const int h_size[10] = {1,4,16,64,256,1024,4096,16384,65536,262144};

// ---------------- static scratch -------------------------------------------
__device__ float HBUF[TOTAL * 128];                       // in_proj fp32 (pool base)
__device__ __align__(16) __nv_bfloat16 HSH[TOTAL * 128];  // split of final h rows
__device__ __align__(16) __nv_bfloat16 HSL[TOTAL * 128];
__device__ __align__(16) __nv_bfloat16 HCH[OFF9 * 128];   // conv outputs split
__device__ __align__(16) __nv_bfloat16 HCL[OFF9 * 128];
__device__ __align__(16) __nv_bfloat16 XH[TOTAL * 64];    // posenc split (64-padded)
__device__ __align__(16) __nv_bfloat16 XL[TOTAL * 64];
__device__ float HACC[KS * SLICE];                        // split-K partials (d<=6)
// prepacked bf16 hi/lo weight chunk images: [tile][j=128][k=32]
__device__ __align__(16) __nv_bfloat16 WIH[2*4096],     WIL[2*4096];
__device__ __align__(16) __nv_bfloat16 WCH[10*36*4096], WCL[10*36*4096];
__device__ __align__(16) __nv_bfloat16 WEH[10*4*4096],  WEL[10*4*4096];

// ---------------- Morton helpers -------------------------------------------
__device__ __forceinline__ unsigned mi_interleave(unsigned x) {
    x &= 0xFFFFu;
    x = (x | (x << 8)) & 0x00FF00FFu;
    x = (x | (x << 4)) & 0x0F0F0F0Fu;
    x = (x | (x << 2)) & 0x33333333u;
    x = (x | (x << 1)) & 0x55555555u;
    return x;
}
__device__ __forceinline__ unsigned mi_deinterleave(unsigned x) {
    x &= 0x55555555u;
    x = (x | (x >> 1)) & 0x33333333u;
    x = (x | (x >> 2)) & 0x0F0F0F0Fu;
    x = (x | (x >> 4)) & 0x00FF00FFu;
    x = (x | (x >> 8)) & 0xFFFFu;
    return x;
}

// ---------------- PTX helpers ----------------------------------------------
__device__ __forceinline__ uint32_t smem_u32(const void* p) {
    uint32_t a;
    asm("{ .reg .u64 tmp; cvta.to.shared.u64 tmp, %1; cvt.u32.u64 %0, tmp; }"
        : "=r"(a) : "l"(p));
    return a;
}
__device__ __forceinline__ void ldsm4(uint32_t* r, uint32_t addr) {
    asm volatile("ldmatrix.sync.aligned.m8n8.x4.shared.b16 {%0,%1,%2,%3}, [%4];"
        : "=r"(r[0]), "=r"(r[1]), "=r"(r[2]), "=r"(r[3]) : "r"(addr));
}
__device__ __forceinline__ void mma_bf16(float* d, const uint32_t* a, const uint32_t* b) {
    asm volatile(
        "mma.sync.aligned.m16n8k16.row.col.f32.bf16.bf16.f32 "
        "{%0,%1,%2,%3}, {%4,%5,%6,%7}, {%8,%9}, {%0,%1,%2,%3};"
        : "+f"(d[0]), "+f"(d[1]), "+f"(d[2]), "+f"(d[3])
        : "r"(a[0]), "r"(a[1]), "r"(a[2]), "r"(a[3]), "r"(b[0]), "r"(b[1]));
}
__device__ __forceinline__ void cp16(uint32_t dst, const void* src, int srcsize) {
    asm volatile("cp.async.ca.shared.global [%0], [%1], 16, %2;"
                 :: "r"(dst), "l"(src), "r"(srcsize) : "memory");
}
#define CP_COMMIT() asm volatile("cp.async.commit_group;" ::: "memory")
#define CP_WAIT0()  asm volatile("cp.async.wait_group 0;" ::: "memory")

// ---------------- split helper ----------------------------------------------
__device__ __forceinline__ void split2(float a, float b, unsigned& hi, unsigned& lo) {
    __nv_bfloat162 h = __float22bfloat162_rn(make_float2(a, b));
    float2 f = __bfloat1622float2(h);
    __nv_bfloat162 l = __float22bfloat162_rn(make_float2(a - f.x, b - f.y));
    hi = *(unsigned*)&h;
    lo = *(unsigned*)&l;
}

// ---------------- smem buffer geometry --------------------------------------
// per-buffer: Ah[64*80] Al[64*80] Bh[128*80] Bl[128*80] = 30720 bytes, x2 bufs
#define BUFB 30720
#define NBUF 2
#define DSM_BYTES (NBUF * BUFB)
#define AL_OFF 5120
#define BH_OFF 10240
#define BL_OFF 20480

// ---------------- shared compute: one 32-k chunk (per warp 32x32 tile) ------
__device__ __forceinline__ void compute_chunk(uint32_t sb, int warp_m, int warp_n,
                                              int a_row, int a_byte,
                                              int b_row, int b_byte,
                                              float (*acc)[4][4]) {
    uint32_t Ah = sb, Al = sb + AL_OFF, Bh = sb + BH_OFF, Bl = sb + BL_OFF;
#pragma unroll
    for (int kt = 0; kt < 2; kt++) {
        uint32_t ah[2][4], al[2][4];
#pragma unroll
        for (int mt = 0; mt < 2; mt++) {
            uint32_t ao = (uint32_t)((warp_m * 32 + mt * 16 + a_row) * 80 + kt * 32 + a_byte);
            ldsm4(ah[mt], Ah + ao);
            ldsm4(al[mt], Al + ao);
        }
#pragma unroll
        for (int ng = 0; ng < 2; ng++) {
            uint32_t bo = (uint32_t)((warp_n * 32 + ng * 16 + b_row) * 80 + kt * 32 + b_byte);
            uint32_t bh[4], bl[4];
            ldsm4(bh, Bh + bo);
            ldsm4(bl, Bl + bo);
#pragma unroll
            for (int mt = 0; mt < 2; mt++) {
                mma_bf16(acc[mt][ng * 2 + 0], ah[mt], bh);
                mma_bf16(acc[mt][ng * 2 + 1], ah[mt], bh + 2);
            }
#pragma unroll
            for (int mt = 0; mt < 2; mt++) {
                mma_bf16(acc[mt][ng * 2 + 0], ah[mt], bl);
                mma_bf16(acc[mt][ng * 2 + 1], ah[mt], bl + 2);
            }
#pragma unroll
            for (int mt = 0; mt < 2; mt++) {
                mma_bf16(acc[mt][ng * 2 + 0], al[mt], bh);
                mma_bf16(acc[mt][ng * 2 + 1], al[mt], bh + 2);
            }
        }
    }
}

// ---------------- fused prep (weight split/pack) + per-node posenc -----------
#define NPI (128 * 64)
#define NPC (10 * 128 * 1152)
#define NPE (10 * 128 * 128)
#define PREP_TOTAL (NPI + NPC + NPE)
#define PP_TOTAL (PREP_TOTAL + TOTAL)

__global__ void prep_posenc_kernel(const float* __restrict__ in_proj_W,
                                   const float* __restrict__ conv_W,
                                   const float* __restrict__ emb_W,
                                   const float* __restrict__ feats) {
    int i0 = blockIdx.x * blockDim.x + threadIdx.x;
    if (i0 < PREP_TOTAL) {
        int i = i0;
        float val; int tile, j, kr;
        __nv_bfloat16 *WH, *WL;
        if (i < NPI) {
            j = i >> 6; int k = i & 63;
            tile = k >> 5; kr = k & 31;
            val = (k < 40) ? in_proj_W[j * 40 + k] : 0.f;
            WH = WIH; WL = WIL;
        } else if (i < NPI + NPC) {
            int r = i - NPI;
            int d = r / 147456;
            int rr = r % 147456;
            j = rr / 1152;
            int k = rr % 1152;
            tile = d * 36 + (k >> 5); kr = k & 31;
            val = conv_W[r];
            WH = WCH; WL = WCL;
        } else {
            int r = i - NPI - NPC;
            int d = r / 16384;
            int rr = r % 16384;
            j = rr >> 7;
            int k = rr & 127;
            tile = d * 4 + (k >> 5); kr = k & 31;
            val = emb_W[r];
            WH = WEH; WL = WEL;
        }
        __nv_bfloat16 hi = __float2bfloat16_rn(val);
        __nv_bfloat16 lo = __float2bfloat16_rn(val - __bfloat162float(hi));
        size_t idx = ((size_t)tile * 128 + j) * 32 + kr;
        WH[idx] = hi;
        WL[idx] = lo;
        return;
    }
    int node = i0 - PREP_TOTAL;
    if (node >= TOTAL) return;

    // one thread per node: all 40 real columns + 24 zero pad
    int d = 0;
    while (node >= c_off[d + 1]) d++;
    int local = node - c_off[d];
    unsigned ix = mi_deinterleave((unsigned)local);
    unsigned iy = mi_deinterleave((unsigned)local >> 1);
    float inv = 1.f / (float)(1 << d);

    float vals[64];
#pragma unroll
    for (int c = 40; c < 64; c++) vals[c] = 0.f;
    vals[0] = feats[node];
    vals[1] = ((float)ix + 0.5f) * inv;
    vals[2] = ((float)iy + 0.5f) * inv;
    vals[3] = (float)d * (1.f / 9.f);

#pragma unroll
    for (int dim = 0; dim < 3; dim++) {
        float p = vals[1 + dim];
        float s = sinpif(2.f * p);
        float cc = cospif(2.f * p);
#pragma unroll
        for (int f = 0; f < 6; f++) {
            vals[4 + dim * 12 + f] = s;
            vals[4 + dim * 12 + 6 + f] = cc;
            float s2 = 2.f * s * cc;
            float c2 = fmaf(2.f * cc, cc, -1.f);
            s = s2;
            cc = c2;
        }
    }

#pragma unroll
    for (int g = 0; g < 8; g++) {
        unsigned h[4], l[4];
#pragma unroll
        for (int q = 0; q < 4; q++)
            split2(vals[g * 8 + 2 * q], vals[g * 8 + 2 * q + 1], h[q], l[q]);
        *(uint4*)(XH + (size_t)node * 64 + g * 8) = make_uint4(h[0], h[1], h[2], h[3]);
        *(uint4*)(XL + (size_t)node * 64 + g * 8) = make_uint4(l[0], l[1], l[2], l[3]);
    }
}

// ---------------- pooling d9 -> d8, writes HSH/HSL split --------------------
__global__ void pool9_kernel() {
    int u = blockIdx.x * blockDim.x + threadIdx.x;
    if (u >= 65536 * 32) return;
    int p = u >> 5, c4 = (u & 31) * 4;
    const float* s = HBUF + (size_t)(OFF9 + p * 4) * 128 + c4;
    float4 s0 = *(const float4*)(s);
    float4 s1 = *(const float4*)(s + 128);
    float4 s2 = *(const float4*)(s + 256);
    float4 s3 = *(const float4*)(s + 384);
    const float* bp = HBUF + (size_t)(21845 + p) * 128 + c4;
    float4 b = *(const float4*)bp;
    b.x += 0.25f * (s0.x + s1.x + s2.x + s3.x);
    b.y += 0.25f * (s0.y + s1.y + s2.y + s3.y);
    b.z += 0.25f * (s0.z + s1.z + s2.z + s3.z);
    b.w += 0.25f * (s0.w + s1.w + s2.w + s3.w);
    unsigned h0, l0, h1, l1;
    split2(b.x, b.y, h0, l0);
    split2(b.z, b.w, h1, l1);
    size_t o = (size_t)(21845 + p) * 128 + c4;
    *(uint2*)(HSH + o) = make_uint2(h0, h1);
    *(uint2*)(HSL + o) = make_uint2(l0, l1);
}

// ---------------- in_proj: X[N,64] @ W^T -> HBUF fp32 (+ split for d9) ------
__global__ __launch_bounds__(256, 3)
void inproj_mma(const float* __restrict__ bias) {
    extern __shared__ char dsm[];
    int t = threadIdx.x, lane = t & 31, wid = t >> 5;
    int warp_m = wid >> 2, warp_n = wid & 3;
    int base = blockIdx.x * 64;
    uint32_t sb0 = smem_u32(dsm);
    int a_row = (lane & 7) + ((lane >> 3) & 1) * 8, a_byte = (lane >> 4) * 16;
    int b_row = (lane & 7) + ((lane >> 4) & 1) * 8, b_byte = ((lane >> 3) & 1) * 16;
    int s_row = t >> 2, s_seg = t & 3;

    float acc[2][4][4];
#pragma unroll
    for (int a = 0; a < 2; a++)
#pragma unroll
        for (int b = 0; b < 4; b++)
#pragma unroll
            for (int c = 0; c < 4; c++) acc[a][b][c] = 0.f;

    auto issue = [&](int chunk) {
        uint32_t bufu = sb0 + (chunk & 1) * BUFB;
        int node = base + s_row;
        int p = (node < TOTAL) ? 16 : 0;
        size_t ai = (size_t)(node < TOTAL ? node : 0) * 64 + chunk * 32 + s_seg * 8;
        uint32_t ad = bufu + s_row * 80 + s_seg * 16;
        cp16(ad, XH + ai, p);
        cp16(ad + AL_OFF, XL + ai, p);
#pragma unroll
        for (int h = 0; h < 2; h++) {
            int j = s_row + h * 64;
            size_t bi = ((size_t)chunk * 128 + j) * 32 + s_seg * 8;
            uint32_t bd = bufu + BH_OFF + j * 80 + s_seg * 16;
            cp16(bd, WIH + bi, 16);
            cp16(bd + (BL_OFF - BH_OFF), WIL + bi, 16);
        }
    };

    const int KT = 2;
    issue(0); CP_COMMIT();
    for (int c = 0; c < KT; c++) {
        CP_WAIT0();
        __syncthreads();
        if (c + 1 < KT) { issue(c + 1); CP_COMMIT(); }
        compute_chunk(sb0 + (c & 1) * BUFB, warp_m, warp_n, a_row, a_byte, b_row, b_byte, acc);
    }

#pragma unroll
    for (int mt = 0; mt < 2; mt++)
#pragma unroll
        for (int nt = 0; nt < 4; nt++) {
            int col = warp_n * 32 + nt * 8 + (lane & 3) * 2;
            float b0v = bias[col], b1v = bias[col + 1];
            int r0 = base + warp_m * 32 + mt * 16 + (lane >> 2);
#pragma unroll
            for (int hrow = 0; hrow < 2; hrow++) {
                int node = r0 + hrow * 8;
                if (node < TOTAL) {
                    float v0 = acc[mt][nt][hrow * 2 + 0] + b0v;
                    float v1 = acc[mt][nt][hrow * 2 + 1] + b1v;
                    *(float2*)&HBUF[(size_t)node * 128 + col] = make_float2(v0, v1);
                    if (node >= OFF9) {
                        unsigned hh, ll;
                        split2(v0, v1, hh, ll);
                        *(unsigned*)&HSH[(size_t)node * 128 + col] = hh;
                        *(unsigned*)&HSL[(size_t)node * 128 + col] = ll;
                    }
                }
            }
        }
}

// ---------------- quadconv full-K (fused pooling), depths 7..8 ---------------
__global__ __launch_bounds__(256, 3)
void conv_mma(int depth, int off, int off_prev, int N, const float* __restrict__ conv_b) {
    extern __shared__ char dsm[];
    __shared__ int nbs[9 * 64];
    int t = threadIdx.x, lane = t & 31, wid = t >> 5;
    int warp_m = wid >> 2, warp_n = wid & 3;
    int base = blockIdx.x * 64;
    int res = 1 << depth;

    for (int e = t; e < 9 * 64; e += 256) {
        int m = e >> 6, r = e & 63;
        int node = base + r;
        int val = -1;
        if (node < N) {
            unsigned ix = mi_deinterleave((unsigned)node);
            unsigned iy = mi_deinterleave((unsigned)node >> 1);
            int dx = m % 3 - 1, dy = m / 3 - 1;
            int nx = (int)ix + dx, ny = (int)iy + dy;
            if (nx >= 0 && nx < res && ny >= 0 && ny < res)
                val = (int)(mi_interleave((unsigned)nx) | (mi_interleave((unsigned)ny) << 1));
        }
        nbs[m * 64 + r] = val;
    }
    __syncthreads();

    uint32_t sb0 = smem_u32(dsm);
    int a_row = (lane & 7) + ((lane >> 3) & 1) * 8, a_byte = (lane >> 4) * 16;
    int b_row = (lane & 7) + ((lane >> 4) & 1) * 8, b_byte = ((lane >> 3) & 1) * 16;
    int s_row = t >> 2, s_seg = t & 3;
    int tbase = depth * 36;

    float acc[2][4][4];
#pragma unroll
    for (int a = 0; a < 2; a++)
#pragma unroll
        for (int b = 0; b < 4; b++)
#pragma unroll
            for (int c = 0; c < 4; c++) acc[a][b][c] = 0.f;

    auto issue = [&](int chunk) {
        uint32_t bufu = sb0 + (chunk & 1) * BUFB;
        int m = chunk >> 2, c0 = (chunk & 3) * 32;
        int nbi = nbs[m * 64 + s_row];
        int p = (nbi >= 0) ? 16 : 0;
        size_t ai = (size_t)(off + (nbi >= 0 ? nbi : 0)) * 128 + c0 + s_seg * 8;
        uint32_t ad = bufu + s_row * 80 + s_seg * 16;
        cp16(ad, HSH + ai, p);
        cp16(ad + AL_OFF, HSL + ai, p);
#pragma unroll
        for (int h = 0; h < 2; h++) {
            int j = s_row + h * 64;
            size_t bi = ((size_t)(tbase + chunk) * 128 + j) * 32 + s_seg * 8;
            uint32_t bd = bufu + BH_OFF + j * 80 + s_seg * 16;
            cp16(bd, WCH + bi, 16);
            cp16(bd + (BL_OFF - BH_OFF), WCL + bi, 16);
        }
    };

    const int KT = 36;
    issue(0); CP_COMMIT();
    for (int c = 0; c < KT; c++) {
        CP_WAIT0();
        __syncthreads();
        if (c + 1 < KT) { issue(c + 1); CP_COMMIT(); }
        compute_chunk(sb0 + (c & 1) * BUFB, warp_m, warp_n, a_row, a_byte, b_row, b_byte, acc);
    }

#pragma unroll
    for (int mt = 0; mt < 2; mt++)
#pragma unroll
        for (int nt = 0; nt < 4; nt++) {
            int col = warp_n * 32 + nt * 8 + (lane & 3) * 2;
            float b0v = conv_b[depth * 128 + col], b1v = conv_b[depth * 128 + col + 1];
            int rl = warp_m * 32 + mt * 16 + (lane >> 2);
            float v00 = fmaxf(acc[mt][nt][0] + b0v, 0.f);
            float v01 = fmaxf(acc[mt][nt][1] + b1v, 0.f);
            float v10 = fmaxf(acc[mt][nt][2] + b0v, 0.f);
            float v11 = fmaxf(acc[mt][nt][3] + b1v, 0.f);
            if (base + rl < N) {
                unsigned hh, ll;
                split2(v00, v01, hh, ll);
                size_t o = (size_t)(off + base + rl) * 128 + col;
                *(unsigned*)&HCH[o] = hh;
                *(unsigned*)&HCL[o] = ll;
            }
            if (base + rl + 8 < N) {
                unsigned hh, ll;
                split2(v10, v11, hh, ll);
                size_t o = (size_t)(off + base + rl + 8) * 128 + col;
                *(unsigned*)&HCH[o] = hh;
                *(unsigned*)&HCL[o] = ll;
            }
            float s00 = v00; s00 += __shfl_xor_sync(~0u, s00, 4); s00 += __shfl_xor_sync(~0u, s00, 8);
            float s01 = v01; s01 += __shfl_xor_sync(~0u, s01, 4); s01 += __shfl_xor_sync(~0u, s01, 8);
            float s10 = v10; s10 += __shfl_xor_sync(~0u, s10, 4); s10 += __shfl_xor_sync(~0u, s10, 8);
            float s11 = v11; s11 += __shfl_xor_sync(~0u, s11, 4); s11 += __shfl_xor_sync(~0u, s11, 8);
            if ((lane & 12) == 0) {
#pragma unroll
                for (int g = 0; g < 2; g++) {
                    int q = base + rl + g * 8;
                    float sa = g ? s10 : s00, sb = g ? s11 : s01;
                    if (q + 3 < N) {
                        size_t o = (size_t)(off_prev + (q >> 2)) * 128 + col;
                        float pv0 = HBUF[o] + 0.25f * sa;
                        float pv1 = HBUF[o + 1] + 0.25f * sb;
                        unsigned hh, ll;
                        split2(pv0, pv1, hh, ll);
                        *(unsigned*)&HSH[o] = hh;
                        *(unsigned*)&HSL[o] = ll;
                    }
                }
            }
        }
}

// ---------------- split-K conv for small depths (d <= 6) ---------------------
// grid = tiles * KS; block (tile, ks) computes chunks [ks*6, ks*6+6) and
// stores its fp32 partial tile into HACC[ks].
__global__ __launch_bounds__(256, 3)
void convk_mma(int depth, int off, int N, int tiles) {
    extern __shared__ char dsm[];
    __shared__ int nbs[9 * 64];
    int t = threadIdx.x, lane = t & 31, wid = t >> 5;
    int warp_m = wid >> 2, warp_n = wid & 3;
    int tile = blockIdx.x % tiles;
    int ks = blockIdx.x / tiles;
    int base = tile * 64;
    int res = 1 << depth;

    for (int e = t; e < 9 * 64; e += 256) {
        int m = e >> 6, r = e & 63;
        int node = base + r;
        int val = -1;
        if (node < N) {
            unsigned ix = mi_deinterleave((unsigned)node);
            unsigned iy = mi_deinterleave((unsigned)node >> 1);
            int dx = m % 3 - 1, dy = m / 3 - 1;
            int nx = (int)ix + dx, ny = (int)iy + dy;
            if (nx >= 0 && nx < res && ny >= 0 && ny < res)
                val = (int)(mi_interleave((unsigned)nx) | (mi_interleave((unsigned)ny) << 1));
        }
        nbs[m * 64 + r] = val;
    }
    __syncthreads();

    uint32_t sb0 = smem_u32(dsm);
    int a_row = (lane & 7) + ((lane >> 3) & 1) * 8, a_byte = (lane >> 4) * 16;
    int b_row = (lane & 7) + ((lane >> 4) & 1) * 8, b_byte = ((lane >> 3) & 1) * 16;
    int s_row = t >> 2, s_seg = t & 3;
    int tbase = depth * 36;

    float acc[2][4][4];
#pragma unroll
    for (int a = 0; a < 2; a++)
#pragma unroll
        for (int b = 0; b < 4; b++)
#pragma unroll
            for (int c = 0; c < 4; c++) acc[a][b][c] = 0.f;

    auto issue = [&](int chunk) {
        uint32_t bufu = sb0 + (chunk & 1) * BUFB;
        int m = chunk >> 2, c0 = (chunk & 3) * 32;
        int nbi = nbs[m * 64 + s_row];
        int p = (nbi >= 0) ? 16 : 0;
        size_t ai = (size_t)(off + (nbi >= 0 ? nbi : 0)) * 128 + c0 + s_seg * 8;
        uint32_t ad = bufu + s_row * 80 + s_seg * 16;
        cp16(ad, HSH + ai, p);
        cp16(ad + AL_OFF, HSL + ai, p);
#pragma unroll
        for (int h = 0; h < 2; h++) {
            int j = s_row + h * 64;
            size_t bi = ((size_t)(tbase + chunk) * 128 + j) * 32 + s_seg * 8;
            uint32_t bd = bufu + BH_OFF + j * 80 + s_seg * 16;
            cp16(bd, WCH + bi, 16);
            cp16(bd + (BL_OFF - BH_OFF), WCL + bi, 16);
        }
    };

    int cfirst = ks * 6;
    issue(cfirst); CP_COMMIT();
    for (int cc = 0; cc < 6; cc++) {
        int c = cfirst + cc;
        CP_WAIT0();
        __syncthreads();
        if (cc + 1 < 6) { issue(c + 1); CP_COMMIT(); }
        compute_chunk(sb0 + (c & 1) * BUFB, warp_m, warp_n, a_row, a_byte, b_row, b_byte, acc);
    }

    // store fp32 partials into HACC[ks]
    float* dstb = HACC + (size_t)ks * SLICE;
#pragma unroll
    for (int mt = 0; mt < 2; mt++)
#pragma unroll
        for (int nt = 0; nt < 4; nt++) {
            int col = warp_n * 32 + nt * 8 + (lane & 3) * 2;
            int r0 = base + warp_m * 32 + mt * 16 + (lane >> 2);
#pragma unroll
            for (int hrow = 0; hrow < 2; hrow++) {
                int node = r0 + hrow * 8;
                if (node < N)
                    *(float2*)&dstb[(size_t)(off + node) * 128 + col] =
                        make_float2(acc[mt][nt][hrow * 2 + 0], acc[mt][nt][hrow * 2 + 1]);
            }
        }
}

// reduce partials + bias + relu + split, plus quad pooling into HSH/HSL
__global__ void conv_epi_kernel(int depth, int off, int off_prev, int N,
                                const float* __restrict__ conv_b) {
    int u = blockIdx.x * blockDim.x + threadIdx.x;
    int P = N >> 2;
    if (u >= P * 128) return;
    int p = u >> 7, c = u & 127;
    float bias = conv_b[depth * 128 + c];
    float psum = 0.f;
#pragma unroll
    for (int i = 0; i < 4; i++) {
        size_t idx = (size_t)(off + p * 4 + i) * 128 + c;
        float v = bias;
#pragma unroll
        for (int ks = 0; ks < KS; ks++) v += HACC[(size_t)ks * SLICE + idx];
        v = fmaxf(v, 0.f);
        __nv_bfloat16 hi = __float2bfloat16_rn(v);
        __nv_bfloat16 lo = __float2bfloat16_rn(v - __bfloat162float(hi));
        HCH[idx] = hi;
        HCL[idx] = lo;
        psum += v;
    }
    size_t po = (size_t)(off_prev + p) * 128 + c;
    float pv = HBUF[po] + 0.25f * psum;
    __nv_bfloat16 hi = __float2bfloat16_rn(pv);
    __nv_bfloat16 lo = __float2bfloat16_rn(pv - __bfloat162float(hi));
    HSH[po] = hi;
    HSL[po] = lo;
}

// ---------------- emb GEMM + fused LayerNorm, all depths ---------------------
__global__ __launch_bounds__(256, 3)
void emb_mma(const float* __restrict__ emb_b,
             const float* __restrict__ ln_g,
             const float* __restrict__ ln_b,
             const float* __restrict__ gain_all,
             float* __restrict__ out) {
    extern __shared__ char dsm[];
    int t = threadIdx.x, lane = t & 31, wid = t >> 5;
    int warp_m = wid >> 2, warp_n = wid & 3;
    int b = blockIdx.x;
    int depth = 0;
    while (b >= c_embcum[depth + 1]) depth++;
    int base = (b - c_embcum[depth]) * 64;
    int off = c_off[depth];
    int N = c_off[depth + 1] - off;
    int useC = (depth >= 1 && depth <= 8);
    const __nv_bfloat16* SH = useC ? HCH : HSH;
    const __nv_bfloat16* SL = useC ? HCL : HSL;

    uint32_t sb0 = smem_u32(dsm);
    int a_row = (lane & 7) + ((lane >> 3) & 1) * 8, a_byte = (lane >> 4) * 16;
    int b_row = (lane & 7) + ((lane >> 4) & 1) * 8, b_byte = ((lane >> 3) & 1) * 16;
    int s_row = t >> 2, s_seg = t & 3;
    int tbase = depth * 4;

    float acc[2][4][4];
#pragma unroll
    for (int a = 0; a < 2; a++)
#pragma unroll
        for (int bb = 0; bb < 4; bb++)
#pragma unroll
            for (int c = 0; c < 4; c++) acc[a][bb][c] = 0.f;

    auto issue = [&](int chunk) {
        uint32_t bufu = sb0 + (chunk & 1) * BUFB;
        int node = base + s_row;
        int p = (node < N) ? 16 : 0;
        size_t ai = (size_t)(off + (node < N ? node : 0)) * 128 + chunk * 32 + s_seg * 8;
        uint32_t ad = bufu + s_row * 80 + s_seg * 16;
        cp16(ad, SH + ai, p);
        cp16(ad + AL_OFF, SL + ai, p);
#pragma unroll
        for (int h = 0; h < 2; h++) {
            int j = s_row + h * 64;
            size_t bi = ((size_t)(tbase + chunk) * 128 + j) * 32 + s_seg * 8;
            uint32_t bd = bufu + BH_OFF + j * 80 + s_seg * 16;
            cp16(bd, WEH + bi, 16);
            cp16(bd + (BL_OFF - BH_OFF), WEL + bi, 16);
        }
    };

    const int KT = 4;
    issue(0); CP_COMMIT();
    for (int c = 0; c < KT; c++) {
        CP_WAIT0();
        __syncthreads();
        if (c + 1 < KT) { issue(c + 1); CP_COMMIT(); }
        compute_chunk(sb0 + (c & 1) * BUFB, warp_m, warp_n, a_row, a_byte, b_row, b_byte, acc);
    }
    __syncthreads();

    // dump accumulators to smem [64][132]
    float* C = (float*)dsm;
#pragma unroll
    for (int mt = 0; mt < 2; mt++)
#pragma unroll
        for (int nt = 0; nt < 4; nt++) {
            int rl = warp_m * 32 + mt * 16 + (lane >> 2);
            int col = warp_n * 32 + nt * 8 + (lane & 3) * 2;
            C[rl * 132 + col] = acc[mt][nt][0];
            C[rl * 132 + col + 1] = acc[mt][nt][1];
            C[(rl + 8) * 132 + col] = acc[mt][nt][2];
            C[(rl + 8) * 132 + col + 1] = acc[mt][nt][3];
        }
    __syncthreads();

    // LayerNorm: thread owns (row = t>>2, 32-col segment = t&3)
    int row = t >> 2, seg = t & 3;
    float z[32];
    const float* ebp = &emb_b[depth * 128 + seg * 32];
    float s = 0.f;
#pragma unroll
    for (int i = 0; i < 32; i++) {
        z[i] = C[row * 132 + seg * 32 + i] + ebp[i];
        s += z[i];
    }
    s += __shfl_xor_sync(~0u, s, 1);
    s += __shfl_xor_sync(~0u, s, 2);
    float mu = s * (1.f / 128.f);
    float q = 0.f;
#pragma unroll
    for (int i = 0; i < 32; i++) { z[i] -= mu; q += z[i] * z[i]; }
    q += __shfl_xor_sync(~0u, q, 1);
    q += __shfl_xor_sync(~0u, q, 2);
    float rs = rsqrtf(q * (1.f / 128.f) + 1e-5f);
    if (base + row < N) {
        const float* lgp = &ln_g[depth * 128 + seg * 32];
        const float* lbp = &ln_b[depth * 128 + seg * 32];
        float gain = gain_all[depth];
        float* dst = &out[(size_t)(off + base + row) * 128 + seg * 32];
#pragma unroll
        for (int i = 0; i < 32; i += 4) {
            float4 o;
            o.x = gain * (z[i] * rs * lgp[i] + lbp[i]);
            o.y = gain * (z[i + 1] * rs * lgp[i + 1] + lbp[i + 1]);
            o.z = gain * (z[i + 2] * rs * lgp[i + 2] + lbp[i + 2]);
            o.w = gain * (z[i + 3] * rs * lgp[i + 3] + lbp[i + 3]);
            *(float4*)(dst + i) = o;
        }
    }
}

// ---------------------------------------------------------------------------
extern "C" void kernel_launch(void* const* d_in, const int* in_sizes, int n_in,
                              void* d_out, int out_size) {
    const float* feats     = (const float*)d_in[0];
    const float* in_proj_W = (const float*)d_in[1];
    const float* in_proj_b = (const float*)d_in[2];
    const float* conv_W    = (const float*)d_in[3];
    const float* conv_b    = (const float*)d_in[4];
    const float* emb_W     = (const float*)d_in[5];
    const float* emb_b     = (const float*)d_in[6];
    const float* ln_g      = (const float*)d_in[7];
    const float* ln_b      = (const float*)d_in[8];
    const float* gain      = (const float*)d_in[9];
    float* out = (float*)d_out;

    cudaFuncSetAttribute(inproj_mma, cudaFuncAttributeMaxDynamicSharedMemorySize, DSM_BYTES);
    cudaFuncSetAttribute(conv_mma, cudaFuncAttributeMaxDynamicSharedMemorySize, DSM_BYTES);
    cudaFuncSetAttribute(convk_mma, cudaFuncAttributeMaxDynamicSharedMemorySize, DSM_BYTES);
    cudaFuncSetAttribute(emb_mma, cudaFuncAttributeMaxDynamicSharedMemorySize, DSM_BYTES);

    prep_posenc_kernel<<<(PP_TOTAL + 255) / 256, 256>>>(in_proj_W, conv_W, emb_W, feats);
    inproj_mma<<<(TOTAL + 63) / 64, 256, DSM_BYTES>>>(in_proj_b);
    pool9_kernel<<<(65536 * 32 + 255) / 256, 256>>>();
    for (int dc = 8; dc >= 1; dc--) {
        if (dc >= 7) {
            conv_mma<<<(h_size[dc] + 63) / 64, 256, DSM_BYTES>>>(
                dc, h_off[dc], h_off[dc - 1], h_size[dc], conv_b);
        } else {
            int tiles = (h_size[dc] + 63) / 64;
            convk_mma<<<tiles * KS, 256, DSM_BYTES>>>(dc, h_off[dc], h_size[dc], tiles);
            conv_epi_kernel<<<((h_size[dc] >> 2) * 128 + 255) / 256, 256>>>(
                dc, h_off[dc], h_off[dc - 1], h_size[dc], conv_b);
        }
    }
    emb_mma<<<5464, 256, DSM_BYTES>>>(emb_b, ln_g, ln_b, gain, out);
}

// round 16
// speedup vs baseline: 1.5090x; 1.0223x over previous
#include <cuda_runtime.h>
#include <cuda_bf16.h>
#include <math.h>
#include <stdint.h>

// ---------------------------------------------------------------------------
// TreeEncoder via mma.sync bf16 split-GEMM (hi/lo, 3 products, fp32 accum).
// GEMM core = R11/R14 winner: 64x128 block tile, 256 threads, K-chunk 32,
// NBUF=2 cp.async double buffer, launch_bounds(256,3).
// R16: split-K extended to depth 7 (SLICE widened); inproj skips HBUF stores
// for depth-9 rows (pool9 reconstructs children from HSH+HSL instead).
// ---------------------------------------------------------------------------

#define MAX_DEPTH 9
#define TOTAL 349525
#define OFF9  87381
#define KS 6
#define SLICE (21845 * 128)   // covers nodes of depths 0..7 (off+N <= 21845)

__constant__ int c_off[11] = {0,1,5,21,85,341,1365,5461,21845,87381,349525};
// blocks per depth at 64 rows: 1,1,1,1,4,16,64,256,1024,4096
__constant__ int c_embcum[11] = {0,1,2,3,4,8,24,88,344,1368,5464};

static const int h_off[11]  = {0,1,5,21,85,341,1365,5461,21845,87381,349525};
static const int h_size[10] = {1,4,16,64,256,1024,4096,16384,65536,262144};

// ---------------- static scratch -------------------------------------------
__device__ float HBUF[OFF9 * 128];                        // pool-base rows, d<=8
__device__ __align__(16) __nv_bfloat16 HSH[TOTAL * 128];  // split of final h rows
__device__ __align__(16) __nv_bfloat16 HSL[TOTAL * 128];
__device__ __align__(16) __nv_bfloat16 HCH[OFF9 * 128];   // conv outputs split
__device__ __align__(16) __nv_bfloat16 HCL[OFF9 * 128];
__device__ __align__(16) __nv_bfloat16 XH[TOTAL * 64];    // posenc split (64-padded)
__device__ __align__(16) __nv_bfloat16 XL[TOTAL * 64];
__device__ float HACC[KS * SLICE];                        // split-K partials (d<=7)
// prepacked bf16 hi/lo weight chunk images: [tile][j=128][k=32]
__device__ __align__(16) __nv_bfloat16 WIH[2*4096],     WIL[2*4096];
__device__ __align__(16) __nv_bfloat16 WCH[10*36*4096], WCL[10*36*4096];
__device__ __align__(16) __nv_bfloat16 WEH[10*4*4096],  WEL[10*4*4096];

// ---------------- Morton helpers -------------------------------------------
__device__ __forceinline__ unsigned mi_interleave(unsigned x) {
    x &= 0xFFFFu;
    x = (x | (x << 8)) & 0x00FF00FFu;
    x = (x | (x << 4)) & 0x0F0F0F0Fu;
    x = (x | (x << 2)) & 0x33333333u;
    x = (x | (x << 1)) & 0x55555555u;
    return x;
}
__device__ __forceinline__ unsigned mi_deinterleave(unsigned x) {
    x &= 0x55555555u;
    x = (x | (x >> 1)) & 0x33333333u;
    x = (x | (x >> 2)) & 0x0F0F0F0Fu;
    x = (x | (x >> 4)) & 0x00FF00FFu;
    x = (x | (x >> 8)) & 0xFFFFu;
    return x;
}

// ---------------- PTX helpers ----------------------------------------------
__device__ __forceinline__ uint32_t smem_u32(const void* p) {
    uint32_t a;
    asm("{ .reg .u64 tmp; cvta.to.shared.u64 tmp, %1; cvt.u32.u64 %0, tmp; }"
        : "=r"(a) : "l"(p));
    return a;
}
__device__ __forceinline__ void ldsm4(uint32_t* r, uint32_t addr) {
    asm volatile("ldmatrix.sync.aligned.m8n8.x4.shared.b16 {%0,%1,%2,%3}, [%4];"
        : "=r"(r[0]), "=r"(r[1]), "=r"(r[2]), "=r"(r[3]) : "r"(addr));
}
__device__ __forceinline__ void mma_bf16(float* d, const uint32_t* a, const uint32_t* b) {
    asm volatile(
        "mma.sync.aligned.m16n8k16.row.col.f32.bf16.bf16.f32 "
        "{%0,%1,%2,%3}, {%4,%5,%6,%7}, {%8,%9}, {%0,%1,%2,%3};"
        : "+f"(d[0]), "+f"(d[1]), "+f"(d[2]), "+f"(d[3])
        : "r"(a[0]), "r"(a[1]), "r"(a[2]), "r"(a[3]), "r"(b[0]), "r"(b[1]));
}
__device__ __forceinline__ void cp16(uint32_t dst, const void* src, int srcsize) {
    asm volatile("cp.async.ca.shared.global [%0], [%1], 16, %2;"
                 :: "r"(dst), "l"(src), "r"(srcsize) : "memory");
}
#define CP_COMMIT() asm volatile("cp.async.commit_group;" ::: "memory")
#define CP_WAIT0()  asm volatile("cp.async.wait_group 0;" ::: "memory")

// ---------------- split helper ----------------------------------------------
__device__ __forceinline__ void split2(float a, float b, unsigned& hi, unsigned& lo) {
    __nv_bfloat162 h = __float22bfloat162_rn(make_float2(a, b));
    float2 f = __bfloat1622float2(h);
    __nv_bfloat162 l = __float22bfloat162_rn(make_float2(a - f.x, b - f.y));
    hi = *(unsigned*)&h;
    lo = *(unsigned*)&l;
}

// ---------------- smem buffer geometry --------------------------------------
#define BUFB 30720
#define NBUF 2
#define DSM_BYTES (NBUF * BUFB)
#define AL_OFF 5120
#define BH_OFF 10240
#define BL_OFF 20480

// ---------------- shared compute: one 32-k chunk (per warp 32x32 tile) ------
__device__ __forceinline__ void compute_chunk(uint32_t sb, int warp_m, int warp_n,
                                              int a_row, int a_byte,
                                              int b_row, int b_byte,
                                              float (*acc)[4][4]) {
    uint32_t Ah = sb, Al = sb + AL_OFF, Bh = sb + BH_OFF, Bl = sb + BL_OFF;
#pragma unroll
    for (int kt = 0; kt < 2; kt++) {
        uint32_t ah[2][4], al[2][4];
#pragma unroll
        for (int mt = 0; mt < 2; mt++) {
            uint32_t ao = (uint32_t)((warp_m * 32 + mt * 16 + a_row) * 80 + kt * 32 + a_byte);
            ldsm4(ah[mt], Ah + ao);
            ldsm4(al[mt], Al + ao);
        }
#pragma unroll
        for (int ng = 0; ng < 2; ng++) {
            uint32_t bo = (uint32_t)((warp_n * 32 + ng * 16 + b_row) * 80 + kt * 32 + b_byte);
            uint32_t bh[4], bl[4];
            ldsm4(bh, Bh + bo);
            ldsm4(bl, Bl + bo);
#pragma unroll
            for (int mt = 0; mt < 2; mt++) {
                mma_bf16(acc[mt][ng * 2 + 0], ah[mt], bh);
                mma_bf16(acc[mt][ng * 2 + 1], ah[mt], bh + 2);
            }
#pragma unroll
            for (int mt = 0; mt < 2; mt++) {
                mma_bf16(acc[mt][ng * 2 + 0], ah[mt], bl);
                mma_bf16(acc[mt][ng * 2 + 1], ah[mt], bl + 2);
            }
#pragma unroll
            for (int mt = 0; mt < 2; mt++) {
                mma_bf16(acc[mt][ng * 2 + 0], al[mt], bh);
                mma_bf16(acc[mt][ng * 2 + 1], al[mt], bh + 2);
            }
        }
    }
}

// ---------------- fused prep (weight split/pack) + per-node posenc -----------
#define NPI (128 * 64)
#define NPC (10 * 128 * 1152)
#define NPE (10 * 128 * 128)
#define PREP_TOTAL (NPI + NPC + NPE)
#define PP_TOTAL (PREP_TOTAL + TOTAL)

__global__ void prep_posenc_kernel(const float* __restrict__ in_proj_W,
                                   const float* __restrict__ conv_W,
                                   const float* __restrict__ emb_W,
                                   const float* __restrict__ feats) {
    int i0 = blockIdx.x * blockDim.x + threadIdx.x;
    if (i0 < PREP_TOTAL) {
        int i = i0;
        float val; int tile, j, kr;
        __nv_bfloat16 *WH, *WL;
        if (i < NPI) {
            j = i >> 6; int k = i & 63;
            tile = k >> 5; kr = k & 31;
            val = (k < 40) ? in_proj_W[j * 40 + k] : 0.f;
            WH = WIH; WL = WIL;
        } else if (i < NPI + NPC) {
            int r = i - NPI;
            int d = r / 147456;
            int rr = r % 147456;
            j = rr / 1152;
            int k = rr % 1152;
            tile = d * 36 + (k >> 5); kr = k & 31;
            val = conv_W[r];
            WH = WCH; WL = WCL;
        } else {
            int r = i - NPI - NPC;
            int d = r / 16384;
            int rr = r % 16384;
            j = rr >> 7;
            int k = rr & 127;
            tile = d * 4 + (k >> 5); kr = k & 31;
            val = emb_W[r];
            WH = WEH; WL = WEL;
        }
        __nv_bfloat16 hi = __float2bfloat16_rn(val);
        __nv_bfloat16 lo = __float2bfloat16_rn(val - __bfloat162float(hi));
        size_t idx = ((size_t)tile * 128 + j) * 32 + kr;
        WH[idx] = hi;
        WL[idx] = lo;
        return;
    }
    int node = i0 - PREP_TOTAL;
    if (node >= TOTAL) return;

    int d = 0;
    while (node >= c_off[d + 1]) d++;
    int local = node - c_off[d];
    unsigned ix = mi_deinterleave((unsigned)local);
    unsigned iy = mi_deinterleave((unsigned)local >> 1);
    float inv = 1.f / (float)(1 << d);

    float vals[64];
#pragma unroll
    for (int c = 40; c < 64; c++) vals[c] = 0.f;
    vals[0] = feats[node];
    vals[1] = ((float)ix + 0.5f) * inv;
    vals[2] = ((float)iy + 0.5f) * inv;
    vals[3] = (float)d * (1.f / 9.f);

#pragma unroll
    for (int dim = 0; dim < 3; dim++) {
        float p = vals[1 + dim];
        float s = sinpif(2.f * p);
        float cc = cospif(2.f * p);
#pragma unroll
        for (int f = 0; f < 6; f++) {
            vals[4 + dim * 12 + f] = s;
            vals[4 + dim * 12 + 6 + f] = cc;
            float s2 = 2.f * s * cc;
            float c2 = fmaf(2.f * cc, cc, -1.f);
            s = s2;
            cc = c2;
        }
    }

#pragma unroll
    for (int g = 0; g < 8; g++) {
        unsigned h[4], l[4];
#pragma unroll
        for (int q = 0; q < 4; q++)
            split2(vals[g * 8 + 2 * q], vals[g * 8 + 2 * q + 1], h[q], l[q]);
        *(uint4*)(XH + (size_t)node * 64 + g * 8) = make_uint4(h[0], h[1], h[2], h[3]);
        *(uint4*)(XL + (size_t)node * 64 + g * 8) = make_uint4(l[0], l[1], l[2], l[3]);
    }
}

// ---------------- pooling d9 -> d8 (children reconstructed from HSH+HSL) ----
__global__ void pool9_kernel() {
    int u = blockIdx.x * blockDim.x + threadIdx.x;
    if (u >= 65536 * 32) return;
    int p = u >> 5, c4 = (u & 31) * 4;
    float sum[4] = {0.f, 0.f, 0.f, 0.f};
#pragma unroll
    for (int i = 0; i < 4; i++) {
        size_t o = (size_t)(OFF9 + p * 4 + i) * 128 + c4;
        uint2 hh = *(const uint2*)(HSH + o);
        uint2 ll = *(const uint2*)(HSL + o);
        float2 h0 = __bfloat1622float2(*(__nv_bfloat162*)&hh.x);
        float2 h1 = __bfloat1622float2(*(__nv_bfloat162*)&hh.y);
        float2 l0 = __bfloat1622float2(*(__nv_bfloat162*)&ll.x);
        float2 l1 = __bfloat1622float2(*(__nv_bfloat162*)&ll.y);
        sum[0] += h0.x + l0.x;
        sum[1] += h0.y + l0.y;
        sum[2] += h1.x + l1.x;
        sum[3] += h1.y + l1.y;
    }
    const float* bp = HBUF + (size_t)(21845 + p) * 128 + c4;
    float4 b = *(const float4*)bp;
    b.x += 0.25f * sum[0];
    b.y += 0.25f * sum[1];
    b.z += 0.25f * sum[2];
    b.w += 0.25f * sum[3];
    unsigned h0, l0, h1, l1;
    split2(b.x, b.y, h0, l0);
    split2(b.z, b.w, h1, l1);
    size_t o = (size_t)(21845 + p) * 128 + c4;
    *(uint2*)(HSH + o) = make_uint2(h0, h1);
    *(uint2*)(HSL + o) = make_uint2(l0, l1);
}

// ---------------- in_proj: X[N,64] @ W^T; HBUF for d<=8, split for d9 --------
__global__ __launch_bounds__(256, 3)
void inproj_mma(const float* __restrict__ bias) {
    extern __shared__ char dsm[];
    int t = threadIdx.x, lane = t & 31, wid = t >> 5;
    int warp_m = wid >> 2, warp_n = wid & 3;
    int base = blockIdx.x * 64;
    uint32_t sb0 = smem_u32(dsm);
    int a_row = (lane & 7) + ((lane >> 3) & 1) * 8, a_byte = (lane >> 4) * 16;
    int b_row = (lane & 7) + ((lane >> 4) & 1) * 8, b_byte = ((lane >> 3) & 1) * 16;
    int s_row = t >> 2, s_seg = t & 3;

    float acc[2][4][4];
#pragma unroll
    for (int a = 0; a < 2; a++)
#pragma unroll
        for (int b = 0; b < 4; b++)
#pragma unroll
            for (int c = 0; c < 4; c++) acc[a][b][c] = 0.f;

    auto issue = [&](int chunk) {
        uint32_t bufu = sb0 + (chunk & 1) * BUFB;
        int node = base + s_row;
        int p = (node < TOTAL) ? 16 : 0;
        size_t ai = (size_t)(node < TOTAL ? node : 0) * 64 + chunk * 32 + s_seg * 8;
        uint32_t ad = bufu + s_row * 80 + s_seg * 16;
        cp16(ad, XH + ai, p);
        cp16(ad + AL_OFF, XL + ai, p);
#pragma unroll
        for (int h = 0; h < 2; h++) {
            int j = s_row + h * 64;
            size_t bi = ((size_t)chunk * 128 + j) * 32 + s_seg * 8;
            uint32_t bd = bufu + BH_OFF + j * 80 + s_seg * 16;
            cp16(bd, WIH + bi, 16);
            cp16(bd + (BL_OFF - BH_OFF), WIL + bi, 16);
        }
    };

    const int KT = 2;
    issue(0); CP_COMMIT();
    for (int c = 0; c < KT; c++) {
        CP_WAIT0();
        __syncthreads();
        if (c + 1 < KT) { issue(c + 1); CP_COMMIT(); }
        compute_chunk(sb0 + (c & 1) * BUFB, warp_m, warp_n, a_row, a_byte, b_row, b_byte, acc);
    }

#pragma unroll
    for (int mt = 0; mt < 2; mt++)
#pragma unroll
        for (int nt = 0; nt < 4; nt++) {
            int col = warp_n * 32 + nt * 8 + (lane & 3) * 2;
            float b0v = bias[col], b1v = bias[col + 1];
            int r0 = base + warp_m * 32 + mt * 16 + (lane >> 2);
#pragma unroll
            for (int hrow = 0; hrow < 2; hrow++) {
                int node = r0 + hrow * 8;
                if (node < TOTAL) {
                    float v0 = acc[mt][nt][hrow * 2 + 0] + b0v;
                    float v1 = acc[mt][nt][hrow * 2 + 1] + b1v;
                    if (node < OFF9) {
                        *(float2*)&HBUF[(size_t)node * 128 + col] = make_float2(v0, v1);
                    } else {
                        unsigned hh, ll;
                        split2(v0, v1, hh, ll);
                        *(unsigned*)&HSH[(size_t)node * 128 + col] = hh;
                        *(unsigned*)&HSL[(size_t)node * 128 + col] = ll;
                    }
                }
            }
        }
}

// ---------------- quadconv full-K (fused pooling), depth 8 -------------------
__global__ __launch_bounds__(256, 3)
void conv_mma(int depth, int off, int off_prev, int N, const float* __restrict__ conv_b) {
    extern __shared__ char dsm[];
    __shared__ int nbs[9 * 64];
    int t = threadIdx.x, lane = t & 31, wid = t >> 5;
    int warp_m = wid >> 2, warp_n = wid & 3;
    int base = blockIdx.x * 64;
    int res = 1 << depth;

    for (int e = t; e < 9 * 64; e += 256) {
        int m = e >> 6, r = e & 63;
        int node = base + r;
        int val = -1;
        if (node < N) {
            unsigned ix = mi_deinterleave((unsigned)node);
            unsigned iy = mi_deinterleave((unsigned)node >> 1);
            int dx = m % 3 - 1, dy = m / 3 - 1;
            int nx = (int)ix + dx, ny = (int)iy + dy;
            if (nx >= 0 && nx < res && ny >= 0 && ny < res)
                val = (int)(mi_interleave((unsigned)nx) | (mi_interleave((unsigned)ny) << 1));
        }
        nbs[m * 64 + r] = val;
    }
    __syncthreads();

    uint32_t sb0 = smem_u32(dsm);
    int a_row = (lane & 7) + ((lane >> 3) & 1) * 8, a_byte = (lane >> 4) * 16;
    int b_row = (lane & 7) + ((lane >> 4) & 1) * 8, b_byte = ((lane >> 3) & 1) * 16;
    int s_row = t >> 2, s_seg = t & 3;
    int tbase = depth * 36;

    float acc[2][4][4];
#pragma unroll
    for (int a = 0; a < 2; a++)
#pragma unroll
        for (int b = 0; b < 4; b++)
#pragma unroll
            for (int c = 0; c < 4; c++) acc[a][b][c] = 0.f;

    auto issue = [&](int chunk) {
        uint32_t bufu = sb0 + (chunk & 1) * BUFB;
        int m = chunk >> 2, c0 = (chunk & 3) * 32;
        int nbi = nbs[m * 64 + s_row];
        int p = (nbi >= 0) ? 16 : 0;
        size_t ai = (size_t)(off + (nbi >= 0 ? nbi : 0)) * 128 + c0 + s_seg * 8;
        uint32_t ad = bufu + s_row * 80 + s_seg * 16;
        cp16(ad, HSH + ai, p);
        cp16(ad + AL_OFF, HSL + ai, p);
#pragma unroll
        for (int h = 0; h < 2; h++) {
            int j = s_row + h * 64;
            size_t bi = ((size_t)(tbase + chunk) * 128 + j) * 32 + s_seg * 8;
            uint32_t bd = bufu + BH_OFF + j * 80 + s_seg * 16;
            cp16(bd, WCH + bi, 16);
            cp16(bd + (BL_OFF - BH_OFF), WCL + bi, 16);
        }
    };

    const int KT = 36;
    issue(0); CP_COMMIT();
    for (int c = 0; c < KT; c++) {
        CP_WAIT0();
        __syncthreads();
        if (c + 1 < KT) { issue(c + 1); CP_COMMIT(); }
        compute_chunk(sb0 + (c & 1) * BUFB, warp_m, warp_n, a_row, a_byte, b_row, b_byte, acc);
    }

#pragma unroll
    for (int mt = 0; mt < 2; mt++)
#pragma unroll
        for (int nt = 0; nt < 4; nt++) {
            int col = warp_n * 32 + nt * 8 + (lane & 3) * 2;
            float b0v = conv_b[depth * 128 + col], b1v = conv_b[depth * 128 + col + 1];
            int rl = warp_m * 32 + mt * 16 + (lane >> 2);
            float v00 = fmaxf(acc[mt][nt][0] + b0v, 0.f);
            float v01 = fmaxf(acc[mt][nt][1] + b1v, 0.f);
            float v10 = fmaxf(acc[mt][nt][2] + b0v, 0.f);
            float v11 = fmaxf(acc[mt][nt][3] + b1v, 0.f);
            if (base + rl < N) {
                unsigned hh, ll;
                split2(v00, v01, hh, ll);
                size_t o = (size_t)(off + base + rl) * 128 + col;
                *(unsigned*)&HCH[o] = hh;
                *(unsigned*)&HCL[o] = ll;
            }
            if (base + rl + 8 < N) {
                unsigned hh, ll;
                split2(v10, v11, hh, ll);
                size_t o = (size_t)(off + base + rl + 8) * 128 + col;
                *(unsigned*)&HCH[o] = hh;
                *(unsigned*)&HCL[o] = ll;
            }
            float s00 = v00; s00 += __shfl_xor_sync(~0u, s00, 4); s00 += __shfl_xor_sync(~0u, s00, 8);
            float s01 = v01; s01 += __shfl_xor_sync(~0u, s01, 4); s01 += __shfl_xor_sync(~0u, s01, 8);
            float s10 = v10; s10 += __shfl_xor_sync(~0u, s10, 4); s10 += __shfl_xor_sync(~0u, s10, 8);
            float s11 = v11; s11 += __shfl_xor_sync(~0u, s11, 4); s11 += __shfl_xor_sync(~0u, s11, 8);
            if ((lane & 12) == 0) {
#pragma unroll
                for (int g = 0; g < 2; g++) {
                    int q = base + rl + g * 8;
                    float sa = g ? s10 : s00, sb = g ? s11 : s01;
                    if (q + 3 < N) {
                        size_t o = (size_t)(off_prev + (q >> 2)) * 128 + col;
                        float pv0 = HBUF[o] + 0.25f * sa;
                        float pv1 = HBUF[o + 1] + 0.25f * sb;
                        unsigned hh, ll;
                        split2(pv0, pv1, hh, ll);
                        *(unsigned*)&HSH[o] = hh;
                        *(unsigned*)&HSL[o] = ll;
                    }
                }
            }
        }
}

// ---------------- split-K conv for depths 1..7 -------------------------------
__global__ __launch_bounds__(256, 3)
void convk_mma(int depth, int off, int N, int tiles) {
    extern __shared__ char dsm[];
    __shared__ int nbs[9 * 64];
    int t = threadIdx.x, lane = t & 31, wid = t >> 5;
    int warp_m = wid >> 2, warp_n = wid & 3;
    int tile = blockIdx.x % tiles;
    int ks = blockIdx.x / tiles;
    int base = tile * 64;
    int res = 1 << depth;

    for (int e = t; e < 9 * 64; e += 256) {
        int m = e >> 6, r = e & 63;
        int node = base + r;
        int val = -1;
        if (node < N) {
            unsigned ix = mi_deinterleave((unsigned)node);
            unsigned iy = mi_deinterleave((unsigned)node >> 1);
            int dx = m % 3 - 1, dy = m / 3 - 1;
            int nx = (int)ix + dx, ny = (int)iy + dy;
            if (nx >= 0 && nx < res && ny >= 0 && ny < res)
                val = (int)(mi_interleave((unsigned)nx) | (mi_interleave((unsigned)ny) << 1));
        }
        nbs[m * 64 + r] = val;
    }
    __syncthreads();

    uint32_t sb0 = smem_u32(dsm);
    int a_row = (lane & 7) + ((lane >> 3) & 1) * 8, a_byte = (lane >> 4) * 16;
    int b_row = (lane & 7) + ((lane >> 4) & 1) * 8, b_byte = ((lane >> 3) & 1) * 16;
    int s_row = t >> 2, s_seg = t & 3;
    int tbase = depth * 36;

    float acc[2][4][4];
#pragma unroll
    for (int a = 0; a < 2; a++)
#pragma unroll
        for (int b = 0; b < 4; b++)
#pragma unroll
            for (int c = 0; c < 4; c++) acc[a][b][c] = 0.f;

    auto issue = [&](int chunk) {
        uint32_t bufu = sb0 + (chunk & 1) * BUFB;
        int m = chunk >> 2, c0 = (chunk & 3) * 32;
        int nbi = nbs[m * 64 + s_row];
        int p = (nbi >= 0) ? 16 : 0;
        size_t ai = (size_t)(off + (nbi >= 0 ? nbi : 0)) * 128 + c0 + s_seg * 8;
        uint32_t ad = bufu + s_row * 80 + s_seg * 16;
        cp16(ad, HSH + ai, p);
        cp16(ad + AL_OFF, HSL + ai, p);
#pragma unroll
        for (int h = 0; h < 2; h++) {
            int j = s_row + h * 64;
            size_t bi = ((size_t)(tbase + chunk) * 128 + j) * 32 + s_seg * 8;
            uint32_t bd = bufu + BH_OFF + j * 80 + s_seg * 16;
            cp16(bd, WCH + bi, 16);
            cp16(bd + (BL_OFF - BH_OFF), WCL + bi, 16);
        }
    };

    int cfirst = ks * 6;
    issue(cfirst); CP_COMMIT();
    for (int cc = 0; cc < 6; cc++) {
        int c = cfirst + cc;
        CP_WAIT0();
        __syncthreads();
        if (cc + 1 < 6) { issue(c + 1); CP_COMMIT(); }
        compute_chunk(sb0 + (c & 1) * BUFB, warp_m, warp_n, a_row, a_byte, b_row, b_byte, acc);
    }

    float* dstb = HACC + (size_t)ks * SLICE;
#pragma unroll
    for (int mt = 0; mt < 2; mt++)
#pragma unroll
        for (int nt = 0; nt < 4; nt++) {
            int col = warp_n * 32 + nt * 8 + (lane & 3) * 2;
            int r0 = base + warp_m * 32 + mt * 16 + (lane >> 2);
#pragma unroll
            for (int hrow = 0; hrow < 2; hrow++) {
                int node = r0 + hrow * 8;
                if (node < N)
                    *(float2*)&dstb[(size_t)(off + node) * 128 + col] =
                        make_float2(acc[mt][nt][hrow * 2 + 0], acc[mt][nt][hrow * 2 + 1]);
            }
        }
}

// reduce partials + bias + relu + split, plus quad pooling into HSH/HSL
__global__ void conv_epi_kernel(int depth, int off, int off_prev, int N,
                                const float* __restrict__ conv_b) {
    int u = blockIdx.x * blockDim.x + threadIdx.x;
    int P = N >> 2;
    if (u >= P * 128) return;
    int p = u >> 7, c = u & 127;
    float bias = conv_b[depth * 128 + c];
    float psum = 0.f;
#pragma unroll
    for (int i = 0; i < 4; i++) {
        size_t idx = (size_t)(off + p * 4 + i) * 128 + c;
        float v = bias;
#pragma unroll
        for (int ks = 0; ks < KS; ks++) v += HACC[(size_t)ks * SLICE + idx];
        v = fmaxf(v, 0.f);
        __nv_bfloat16 hi = __float2bfloat16_rn(v);
        __nv_bfloat16 lo = __float2bfloat16_rn(v - __bfloat162float(hi));
        HCH[idx] = hi;
        HCL[idx] = lo;
        psum += v;
    }
    size_t po = (size_t)(off_prev + p) * 128 + c;
    float pv = HBUF[po] + 0.25f * psum;
    __nv_bfloat16 hi = __float2bfloat16_rn(pv);
    __nv_bfloat16 lo = __float2bfloat16_rn(pv - __bfloat162float(hi));
    HSH[po] = hi;
    HSL[po] = lo;
}

// ---------------- emb GEMM + fused LayerNorm, all depths ---------------------
__global__ __launch_bounds__(256, 3)
void emb_mma(const float* __restrict__ emb_b,
             const float* __restrict__ ln_g,
             const float* __restrict__ ln_b,
             const float* __restrict__ gain_all,
             float* __restrict__ out) {
    extern __shared__ char dsm[];
    int t = threadIdx.x, lane = t & 31, wid = t >> 5;
    int warp_m = wid >> 2, warp_n = wid & 3;
    int b = blockIdx.x;
    int depth = 0;
    while (b >= c_embcum[depth + 1]) depth++;
    int base = (b - c_embcum[depth]) * 64;
    int off = c_off[depth];
    int N = c_off[depth + 1] - off;
    int useC = (depth >= 1 && depth <= 8);
    const __nv_bfloat16* SH = useC ? HCH : HSH;
    const __nv_bfloat16* SL = useC ? HCL : HSL;

    uint32_t sb0 = smem_u32(dsm);
    int a_row = (lane & 7) + ((lane >> 3) & 1) * 8, a_byte = (lane >> 4) * 16;
    int b_row = (lane & 7) + ((lane >> 4) & 1) * 8, b_byte = ((lane >> 3) & 1) * 16;
    int s_row = t >> 2, s_seg = t & 3;
    int tbase = depth * 4;

    float acc[2][4][4];
#pragma unroll
    for (int a = 0; a < 2; a++)
#pragma unroll
        for (int bb = 0; bb < 4; bb++)
#pragma unroll
            for (int c = 0; c < 4; c++) acc[a][bb][c] = 0.f;

    auto issue = [&](int chunk) {
        uint32_t bufu = sb0 + (chunk & 1) * BUFB;
        int node = base + s_row;
        int p = (node < N) ? 16 : 0;
        size_t ai = (size_t)(off + (node < N ? node : 0)) * 128 + chunk * 32 + s_seg * 8;
        uint32_t ad = bufu + s_row * 80 + s_seg * 16;
        cp16(ad, SH + ai, p);
        cp16(ad + AL_OFF, SL + ai, p);
#pragma unroll
        for (int h = 0; h < 2; h++) {
            int j = s_row + h * 64;
            size_t bi = ((size_t)(tbase + chunk) * 128 + j) * 32 + s_seg * 8;
            uint32_t bd = bufu + BH_OFF + j * 80 + s_seg * 16;
            cp16(bd, WEH + bi, 16);
            cp16(bd + (BL_OFF - BH_OFF), WEL + bi, 16);
        }
    };

    const int KT = 4;
    issue(0); CP_COMMIT();
    for (int c = 0; c < KT; c++) {
        CP_WAIT0();
        __syncthreads();
        if (c + 1 < KT) { issue(c + 1); CP_COMMIT(); }
        compute_chunk(sb0 + (c & 1) * BUFB, warp_m, warp_n, a_row, a_byte, b_row, b_byte, acc);
    }
    __syncthreads();

    // dump accumulators to smem [64][132]
    float* C = (float*)dsm;
#pragma unroll
    for (int mt = 0; mt < 2; mt++)
#pragma unroll
        for (int nt = 0; nt < 4; nt++) {
            int rl = warp_m * 32 + mt * 16 + (lane >> 2);
            int col = warp_n * 32 + nt * 8 + (lane & 3) * 2;
            C[rl * 132 + col] = acc[mt][nt][0];
            C[rl * 132 + col + 1] = acc[mt][nt][1];
            C[(rl + 8) * 132 + col] = acc[mt][nt][2];
            C[(rl + 8) * 132 + col + 1] = acc[mt][nt][3];
        }
    __syncthreads();

    // LayerNorm: thread owns (row = t>>2, 32-col segment = t&3)
    int row = t >> 2, seg = t & 3;
    float z[32];
    const float* ebp = &emb_b[depth * 128 + seg * 32];
    float s = 0.f;
#pragma unroll
    for (int i = 0; i < 32; i++) {
        z[i] = C[row * 132 + seg * 32 + i] + ebp[i];
        s += z[i];
    }
    s += __shfl_xor_sync(~0u, s, 1);
    s += __shfl_xor_sync(~0u, s, 2);
    float mu = s * (1.f / 128.f);
    float q = 0.f;
#pragma unroll
    for (int i = 0; i < 32; i++) { z[i] -= mu; q += z[i] * z[i]; }
    q += __shfl_xor_sync(~0u, q, 1);
    q += __shfl_xor_sync(~0u, q, 2);
    float rs = rsqrtf(q * (1.f / 128.f) + 1e-5f);
    if (base + row < N) {
        const float* lgp = &ln_g[depth * 128 + seg * 32];
        const float* lbp = &ln_b[depth * 128 + seg * 32];
        float gain = gain_all[depth];
        float* dst = &out[(size_t)(off + base + row) * 128 + seg * 32];
#pragma unroll
        for (int i = 0; i < 32; i += 4) {
            float4 o;
            o.x = gain * (z[i] * rs * lgp[i] + lbp[i]);
            o.y = gain * (z[i + 1] * rs * lgp[i + 1] + lbp[i + 1]);
            o.z = gain * (z[i + 2] * rs * lgp[i + 2] + lbp[i + 2]);
            o.w = gain * (z[i + 3] * rs * lgp[i + 3] + lbp[i + 3]);
            *(float4*)(dst + i) = o;
        }
    }
}

// ---------------------------------------------------------------------------
extern "C" void kernel_launch(void* const* d_in, const int* in_sizes, int n_in,
                              void* d_out, int out_size) {
    const float* feats     = (const float*)d_in[0];
    const float* in_proj_W = (const float*)d_in[1];
    const float* in_proj_b = (const float*)d_in[2];
    const float* conv_W    = (const float*)d_in[3];
    const float* conv_b    = (const float*)d_in[4];
    const float* emb_W     = (const float*)d_in[5];
    const float* emb_b     = (const float*)d_in[6];
    const float* ln_g      = (const float*)d_in[7];
    const float* ln_b      = (const float*)d_in[8];
    const float* gain      = (const float*)d_in[9];
    float* out = (float*)d_out;

    cudaFuncSetAttribute(inproj_mma, cudaFuncAttributeMaxDynamicSharedMemorySize, DSM_BYTES);
    cudaFuncSetAttribute(conv_mma, cudaFuncAttributeMaxDynamicSharedMemorySize, DSM_BYTES);
    cudaFuncSetAttribute(convk_mma, cudaFuncAttributeMaxDynamicSharedMemorySize, DSM_BYTES);
    cudaFuncSetAttribute(emb_mma, cudaFuncAttributeMaxDynamicSharedMemorySize, DSM_BYTES);

    prep_posenc_kernel<<<(PP_TOTAL + 255) / 256, 256>>>(in_proj_W, conv_W, emb_W, feats);
    inproj_mma<<<(TOTAL + 63) / 64, 256, DSM_BYTES>>>(in_proj_b);
    pool9_kernel<<<(65536 * 32 + 255) / 256, 256>>>();
    for (int dc = 8; dc >= 1; dc--) {
        if (dc >= 8) {
            conv_mma<<<(h_size[dc] + 63) / 64, 256, DSM_BYTES>>>(
                dc, h_off[dc], h_off[dc - 1], h_size[dc], conv_b);
        } else {
            int tiles = (h_size[dc] + 63) / 64;
            convk_mma<<<tiles * KS, 256, DSM_BYTES>>>(dc, h_off[dc], h_size[dc], tiles);
            conv_epi_kernel<<<((h_size[dc] >> 2) * 128 + 255) / 256, 256>>>(
                dc, h_off[dc], h_off[dc - 1], h_size[dc], conv_b);
        }
    }
    emb_mma<<<5464, 256, DSM_BYTES>>>(emb_b, ln_g, ln_b, gain, out);
}